// round 2
// baseline (speedup 1.0000x reference)
#include <cuda_runtime.h>
#include <cstdint>

#define N_NODES 4096
#define F_IN 512
#define F_OUT 64
#define NREL 16
#define M_EDGES 262144
#define RPC 4            // rows per CTA in fused kernel
#define FUSED_THREADS 512

// -------------------- scratch (device globals; no allocation) --------------------
__device__ unsigned int g_lr[(size_t)N_NODES * N_NODES];   // encoded scatter-max logits_r
__device__ float g_seq[(size_t)N_NODES * F_OUT];           // seq_fts
__device__ float g_f1[N_NODES];
__device__ float g_f2[N_NODES];

// order-preserving float <-> uint encoding (for atomicMax-as-float-max)
__device__ __forceinline__ unsigned int fenc(float f) {
    unsigned int u = __float_as_uint(f);
    return (u & 0x80000000u) ? ~u : (u | 0x80000000u);
}
__device__ __forceinline__ float fdec(unsigned int k) {
    unsigned int u = (k & 0x80000000u) ? (k ^ 0x80000000u) : ~k;
    return __uint_as_float(u);
}

// -------------------- kernel 1: init scratch with encoded NEG --------------------
__global__ void k_init() {
    unsigned int v = fenc(-1e30f);
    uint4 q = make_uint4(v, v, v, v);
    uint4* p = reinterpret_cast<uint4*>(g_lr);
    const int n = (N_NODES * N_NODES) / 4;
    for (int i = blockIdx.x * blockDim.x + threadIdx.x; i < n; i += gridDim.x * blockDim.x)
        p[i] = q;
}

// -------------------- kernel 2: seq_fts = input @ W_proj^T --------------------
// 16 rows x 64 cols per CTA, 256 threads, K-tiled by 32 through smem.
__global__ void k_gemm(const float* __restrict__ input, const float* __restrict__ W) {
    __shared__ float Ws[32 * 64];   // [kk][f]
    __shared__ float Is[16 * 32];   // [row][kk]
    const int t = threadIdx.x;
    const int row0 = blockIdx.x * 16;
    const int f = t & 63;
    const int rg = t >> 6;          // 0..3
    float acc[4] = {0.f, 0.f, 0.f, 0.f};

    for (int k0 = 0; k0 < F_IN; k0 += 32) {
        __syncthreads();
#pragma unroll
        for (int i = 0; i < 8; i++) {
            int e = t + i * 256;           // 2048 elems
            int ff = e >> 5, kk = e & 31;
            Ws[kk * 64 + ff] = W[ff * F_IN + k0 + kk];
        }
#pragma unroll
        for (int i = 0; i < 2; i++) {
            int e = t + i * 256;           // 512 elems
            int rr = e >> 5, kk = e & 31;
            Is[rr * 32 + kk] = input[(size_t)(row0 + rr) * F_IN + k0 + kk];
        }
        __syncthreads();
#pragma unroll
        for (int kk = 0; kk < 32; kk++) {
            float w = Ws[kk * 64 + f];
#pragma unroll
            for (int i = 0; i < 4; i++)
                acc[i] = fmaf(Is[(rg + 4 * i) * 32 + kk], w, acc[i]);
        }
    }
#pragma unroll
    for (int i = 0; i < 4; i++)
        g_seq[(size_t)(row0 + rg + 4 * i) * F_OUT + f] = acc[i];
}

// -------------------- kernel 3: f1/f2 row dots --------------------
__global__ void k_f1f2(const float* __restrict__ wf1, const float* __restrict__ bf1,
                       const float* __restrict__ wf2, const float* __restrict__ bf2) {
    const int wid = threadIdx.x >> 5, lane = threadIdx.x & 31;
    const int row = blockIdx.x * 4 + wid;
    float a = g_seq[(size_t)row * 64 + lane];
    float b = g_seq[(size_t)row * 64 + 32 + lane];
    float s1 = a * wf1[lane] + b * wf1[32 + lane];
    float s2 = a * wf2[lane] + b * wf2[32 + lane];
#pragma unroll
    for (int o = 16; o; o >>= 1) {
        s1 += __shfl_xor_sync(0xffffffffu, s1, o);
        s2 += __shfl_xor_sync(0xffffffffu, s2, o);
    }
    if (lane == 0) {
        g_f1[row] = s1 + bf1[0];
        g_f2[row] = s2 + bf2[0];
    }
}

// -------------------- kernel 4: rel scores + symmetric scatter-max --------------------
__global__ void k_scatter(const float* __restrict__ rel, const int* __restrict__ e1,
                          const int* __restrict__ e2, const float* __restrict__ wrel) {
    int m = blockIdx.x * blockDim.x + threadIdx.x;
    if (m >= M_EDGES) return;
    const float4* r4 = reinterpret_cast<const float4*>(rel + (size_t)m * NREL);
    const float4* w4 = reinterpret_cast<const float4*>(wrel);
    float s = 0.f;
#pragma unroll
    for (int i = 0; i < 4; i++) {
        float4 a = r4[i], b = w4[i];
        s += a.x * b.x + a.y * b.y + a.z * b.z + a.w * b.w;
    }
    unsigned int k = fenc(s);
    unsigned int i1 = (unsigned int)e1[m], i2 = (unsigned int)e2[m];
    atomicMax(&g_lr[i1 * (unsigned)N_NODES + i2], k);
    atomicMax(&g_lr[i2 * (unsigned)N_NODES + i1], k);
}

// -------------------- block reductions (512 threads, 16 warps) --------------------
__device__ __forceinline__ float bred_max(float v, float* red) {
    int lane = threadIdx.x & 31, w = threadIdx.x >> 5;
#pragma unroll
    for (int o = 16; o; o >>= 1) v = fmaxf(v, __shfl_xor_sync(0xffffffffu, v, o));
    if (lane == 0) red[w] = v;
    __syncthreads();
    if (threadIdx.x < 16) {
        v = red[threadIdx.x];
#pragma unroll
        for (int o = 8; o; o >>= 1) v = fmaxf(v, __shfl_xor_sync(0x0000ffffu, v, o));
        if (threadIdx.x == 0) red[0] = v;
    }
    __syncthreads();
    v = red[0];
    __syncthreads();
    return v;
}
__device__ __forceinline__ float bred_sum(float v, float* red) {
    int lane = threadIdx.x & 31, w = threadIdx.x >> 5;
#pragma unroll
    for (int o = 16; o; o >>= 1) v += __shfl_xor_sync(0xffffffffu, v, o);
    if (lane == 0) red[w] = v;
    __syncthreads();
    if (threadIdx.x < 16) {
        v = red[threadIdx.x];
#pragma unroll
        for (int o = 8; o; o >>= 1) v += __shfl_xor_sync(0x0000ffffu, v, o);
        if (threadIdx.x == 0) red[0] = v;
    }
    __syncthreads();
    v = red[0];
    __syncthreads();
    return v;
}

// -------------------- kernel 5: fused triple-softmax + weighted aggregation --------------------
// Per CTA: RPC rows. smem: A,B,C [RPC*4096] + F2 [4096] + red [64]
__global__ __launch_bounds__(FUSED_THREADS, 1)
void k_fused(const float* __restrict__ adj, const float* __restrict__ adj_ad,
             const float* __restrict__ Wsi, const float* __restrict__ Wei,
             const float* __restrict__ Wri, const float* __restrict__ bias,
             float* __restrict__ out) {
    extern __shared__ float sm[];
    float* A  = sm;                       // a_r -> exp_r -> c -> u
    float* B  = A + RPC * N_NODES;        // a_e -> exp_e -> (reuse: partials)
    float* C  = B + RPC * N_NODES;        // adj_ad staged
    float* F2 = C + RPC * N_NODES;        // f2 vector
    float* red = F2 + N_NODES;            // reduction scratch (64 floats)

    const int t = threadIdx.x;
    const int row0 = blockIdx.x * RPC;
    const unsigned int encneg = fenc(-1e30f);
    const float wS = fabsf(Wsi[0]), wE = fabsf(Wei[0]), wR = fabsf(Wri[0]);

    for (int j = t; j < N_NODES; j += FUSED_THREADS) F2[j] = g_f2[j];
    __syncthreads();

    // ---- phase 1: load rows, compute a_r / a_e, stage adj_ad, track maxima ----
    float mr[RPC], me[RPC];
#pragma unroll
    for (int r = 0; r < RPC; r++) { mr[r] = -3.4e38f; me[r] = -3.4e38f; }
#pragma unroll
    for (int r = 0; r < RPC; r++) {
        const float f1v = g_f1[row0 + r];
        const size_t base = (size_t)(row0 + r) * N_NODES;
        for (int j = t; j < N_NODES; j += FUSED_THREADS) {
            unsigned int k = g_lr[base + j];
            float lr = (k == encneg) ? 0.f : fdec(k);
            lr = (lr > 0.f) ? lr : 0.2f * lr;            // lrelu
            float av = adj[base + j];
            float ar = lr + av;
            float ge = f1v + F2[j];
            ge = (ge > 0.f) ? ge : 0.2f * ge;
            float ae = ge + av;
            A[r * N_NODES + j] = ar;
            B[r * N_NODES + j] = ae;
            C[r * N_NODES + j] = adj_ad[base + j];
            mr[r] = fmaxf(mr[r], ar);
            me[r] = fmaxf(me[r], ae);
        }
    }
    float Mr[RPC], Me[RPC];
#pragma unroll
    for (int r = 0; r < RPC; r++) { Mr[r] = bred_max(mr[r], red); Me[r] = bred_max(me[r], red); }

    // ---- phase 2: exponentials + sums for r and e ----
    float Sr[RPC], Se[RPC];
#pragma unroll
    for (int r = 0; r < RPC; r++) {
        float sr = 0.f, se = 0.f;
        for (int j = t; j < N_NODES; j += FUSED_THREADS) {
            float er = __expf(A[r * N_NODES + j] - Mr[r]);
            A[r * N_NODES + j] = er; sr += er;
            float ee = __expf(B[r * N_NODES + j] - Me[r]);
            B[r * N_NODES + j] = ee; se += ee;
        }
        Sr[r] = bred_sum(sr, red);
        Se[r] = bred_sum(se, red);
    }

    // ---- phase 3: combined logits c, track max ----
    float Mc[RPC];
#pragma unroll
    for (int r = 0; r < RPC; r++) {
        const float cE = wE / Se[r], cR = wR / Sr[r];
        float mc = -3.4e38f;
        for (int j = t; j < N_NODES; j += FUSED_THREADS) {
            float c = fmaf(cE, B[r * N_NODES + j],
                      fmaf(cR, A[r * N_NODES + j], wS * C[r * N_NODES + j]));
            A[r * N_NODES + j] = c;
            mc = fmaxf(mc, c);
        }
        Mc[r] = bred_max(mc, red);
    }

    // ---- phase 4: u = exp(c - max), sums ----
    float Su[RPC];
#pragma unroll
    for (int r = 0; r < RPC; r++) {
        float su = 0.f;
        for (int j = t; j < N_NODES; j += FUSED_THREADS) {
            float u = __expf(A[r * N_NODES + j] - Mc[r]);
            A[r * N_NODES + j] = u;
            su += u;
        }
        Su[r] = bred_sum(su, red);
    }

    // ---- phase 5: h = (u @ seq_fts) / Su + bias, then elu ----
    const int f = t & 63;
    const int g = t >> 6;            // 8 j-groups
    float acc[RPC];
#pragma unroll
    for (int r = 0; r < RPC; r++) acc[r] = 0.f;
    for (int j = g; j < N_NODES; j += 8) {
        float s = g_seq[(size_t)j * F_OUT + f];
#pragma unroll
        for (int r = 0; r < RPC; r++)
            acc[r] = fmaf(A[r * N_NODES + j], s, acc[r]);
    }
    // partial reduction over the 8 groups (reuse B region)
#pragma unroll
    for (int r = 0; r < RPC; r++)
        B[(r * 8 + g) * 64 + f] = acc[r];
    __syncthreads();
    if (t < RPC * 64) {
        int r = t >> 6, ff = t & 63;
        float h = 0.f;
#pragma unroll
        for (int gg = 0; gg < 8; gg++) h += B[(r * 8 + gg) * 64 + ff];
        h = h / Su[r] + bias[ff];
        float o = (h > 0.f) ? h : expm1f(h);   // elu (alpha=1)
        out[(size_t)(row0 + r) * F_OUT + ff] = o;
    }
}

// -------------------- launcher --------------------
extern "C" void kernel_launch(void* const* d_in, const int* in_sizes, int n_in,
                              void* d_out, int out_size) {
    const float* input  = (const float*)d_in[0];
    const float* rel    = (const float*)d_in[1];
    const int*   e1     = (const int*)  d_in[2];
    const int*   e2     = (const int*)  d_in[3];
    const float* adj    = (const float*)d_in[4];
    const float* adj_ad = (const float*)d_in[5];
    const float* Wp     = (const float*)d_in[6];
    const float* wrel   = (const float*)d_in[7];
    const float* wf1    = (const float*)d_in[8];
    const float* bf1    = (const float*)d_in[9];
    const float* wf2    = (const float*)d_in[10];
    const float* bf2    = (const float*)d_in[11];
    const float* bias   = (const float*)d_in[12];
    const float* Wsi    = (const float*)d_in[13];
    const float* Wei    = (const float*)d_in[14];
    const float* Wri    = (const float*)d_in[15];
    float* out = (float*)d_out;

    const size_t fused_smem = (size_t)(3 * RPC * N_NODES + N_NODES + 64) * sizeof(float);
    cudaFuncSetAttribute(k_fused, cudaFuncAttributeMaxDynamicSharedMemorySize, (int)fused_smem);

    k_init<<<2048, 256>>>();
    k_gemm<<<N_NODES / 16, 256>>>(input, Wp);
    k_f1f2<<<N_NODES / 4, 128>>>(wf1, bf1, wf2, bf2);
    k_scatter<<<M_EDGES / 256, 256>>>(rel, e1, e2, wrel);
    k_fused<<<N_NODES / RPC, FUSED_THREADS, fused_smem>>>(adj, adj_ad, Wsi, Wei, Wri, bias, out);
}

// round 3
// speedup vs baseline: 1.8661x; 1.8661x over previous
#include <cuda_runtime.h>
#include <cuda_bf16.h>
#include <cstdint>

#define N_NODES 4096
#define F_IN 512
#define F_OUT 64
#define NREL 16
#define M_EDGES 262144

// -------------------- scratch (device globals; no allocation) --------------------
__device__ unsigned int g_lr[(size_t)N_NODES * N_NODES];     // encoded scatter-max logits_r
__device__ float g_seq[(size_t)N_NODES * F_OUT];             // seq_fts fp32
__device__ float g_f1[N_NODES];
__device__ float g_f2[N_NODES];
__device__ __nv_bfloat16 g_Uh[(size_t)N_NODES * N_NODES];    // coefs hi (bf16)
__device__ __nv_bfloat16 g_Ul[(size_t)N_NODES * N_NODES];    // coefs lo (bf16 residual)
__device__ __nv_bfloat16 g_ShT[(size_t)F_OUT * N_NODES];     // seq_fts hi, transposed [f][j]
__device__ __nv_bfloat16 g_SlT[(size_t)F_OUT * N_NODES];     // seq_fts lo, transposed [f][j]

// order-preserving float <-> uint encoding (atomicMax-as-float-max)
__device__ __forceinline__ unsigned int fenc(float f) {
    unsigned int u = __float_as_uint(f);
    return (u & 0x80000000u) ? ~u : (u | 0x80000000u);
}
__device__ __forceinline__ float fdec(unsigned int k) {
    unsigned int u = (k & 0x80000000u) ? (k ^ 0x80000000u) : ~k;
    return __uint_as_float(u);
}

// -------------------- kernel 1: init scratch with encoded NEG --------------------
__global__ void k_init() {
    unsigned int v = fenc(-1e30f);
    uint4 q = make_uint4(v, v, v, v);
    uint4* p = reinterpret_cast<uint4*>(g_lr);
    const int n = (N_NODES * N_NODES) / 4;
    for (int i = blockIdx.x * blockDim.x + threadIdx.x; i < n; i += gridDim.x * blockDim.x)
        p[i] = q;
}

// -------------------- kernel 2: seq_fts = input @ W_proj^T --------------------
__global__ void k_gemm(const float* __restrict__ input, const float* __restrict__ W) {
    __shared__ float Ws[32 * 64];   // [kk][f]
    __shared__ float Is[16 * 32];   // [row][kk]
    const int t = threadIdx.x;
    const int row0 = blockIdx.x * 16;
    const int f = t & 63;
    const int rg = t >> 6;
    float acc[4] = {0.f, 0.f, 0.f, 0.f};

    for (int k0 = 0; k0 < F_IN; k0 += 32) {
        __syncthreads();
#pragma unroll
        for (int i = 0; i < 8; i++) {
            int e = t + i * 256;
            int ff = e >> 5, kk = e & 31;
            Ws[kk * 64 + ff] = W[ff * F_IN + k0 + kk];
        }
#pragma unroll
        for (int i = 0; i < 2; i++) {
            int e = t + i * 256;
            int rr = e >> 5, kk = e & 31;
            Is[rr * 32 + kk] = input[(size_t)(row0 + rr) * F_IN + k0 + kk];
        }
        __syncthreads();
#pragma unroll
        for (int kk = 0; kk < 32; kk++) {
            float w = Ws[kk * 64 + f];
#pragma unroll
            for (int i = 0; i < 4; i++)
                acc[i] = fmaf(Is[(rg + 4 * i) * 32 + kk], w, acc[i]);
        }
    }
#pragma unroll
    for (int i = 0; i < 4; i++)
        g_seq[(size_t)(row0 + rg + 4 * i) * F_OUT + f] = acc[i];
}

// -------------------- kernel 3: f1/f2 row dots --------------------
__global__ void k_f1f2(const float* __restrict__ wf1, const float* __restrict__ bf1,
                       const float* __restrict__ wf2, const float* __restrict__ bf2) {
    const int wid = threadIdx.x >> 5, lane = threadIdx.x & 31;
    const int row = blockIdx.x * 4 + wid;
    float a = g_seq[(size_t)row * 64 + lane];
    float b = g_seq[(size_t)row * 64 + 32 + lane];
    float s1 = a * wf1[lane] + b * wf1[32 + lane];
    float s2 = a * wf2[lane] + b * wf2[32 + lane];
#pragma unroll
    for (int o = 16; o; o >>= 1) {
        s1 += __shfl_xor_sync(0xffffffffu, s1, o);
        s2 += __shfl_xor_sync(0xffffffffu, s2, o);
    }
    if (lane == 0) {
        g_f1[row] = s1 + bf1[0];
        g_f2[row] = s2 + bf2[0];
    }
}

// -------------------- kernel 3b: split seq_fts into bf16 hi/lo, transposed --------------------
// grid (16, 64), 256 threads: row f = blockIdx.y, col j
__global__ void k_split() {
    const int f = blockIdx.y;
    const int j = blockIdx.x * 256 + threadIdx.x;
    float v = g_seq[(size_t)j * F_OUT + f];
    __nv_bfloat16 h = __float2bfloat16(v);
    float rres = v - __bfloat162float(h);
    g_ShT[(size_t)f * N_NODES + j] = h;
    g_SlT[(size_t)f * N_NODES + j] = __float2bfloat16(rres);
}

// -------------------- kernel 4: rel scores + symmetric scatter-max --------------------
__global__ void k_scatter(const float* __restrict__ rel, const int* __restrict__ e1,
                          const int* __restrict__ e2, const float* __restrict__ wrel) {
    int m = blockIdx.x * blockDim.x + threadIdx.x;
    if (m >= M_EDGES) return;
    const float4* r4 = reinterpret_cast<const float4*>(rel + (size_t)m * NREL);
    const float4* w4 = reinterpret_cast<const float4*>(wrel);
    float s = 0.f;
#pragma unroll
    for (int i = 0; i < 4; i++) {
        float4 a = r4[i], b = w4[i];
        s += a.x * b.x + a.y * b.y + a.z * b.z + a.w * b.w;
    }
    unsigned int k = fenc(s);
    unsigned int i1 = (unsigned int)e1[m], i2 = (unsigned int)e2[m];
    atomicMax(&g_lr[i1 * (unsigned)N_NODES + i2], k);
    atomicMax(&g_lr[i2 * (unsigned)N_NODES + i1], k);
}

// -------------------- block reductions (256 threads, 8 warps) --------------------
__device__ __forceinline__ float bmax(float v, float* red) {
    int lane = threadIdx.x & 31, w = threadIdx.x >> 5;
#pragma unroll
    for (int o = 16; o; o >>= 1) v = fmaxf(v, __shfl_xor_sync(0xffffffffu, v, o));
    if (lane == 0) red[w] = v;
    __syncthreads();
    if (threadIdx.x == 0) {
        float m = red[0];
#pragma unroll
        for (int i = 1; i < 8; i++) m = fmaxf(m, red[i]);
        red[0] = m;
    }
    __syncthreads();
    v = red[0];
    __syncthreads();
    return v;
}
__device__ __forceinline__ float bsum(float v, float* red) {
    int lane = threadIdx.x & 31, w = threadIdx.x >> 5;
#pragma unroll
    for (int o = 16; o; o >>= 1) v += __shfl_xor_sync(0xffffffffu, v, o);
    if (lane == 0) red[w] = v;
    __syncthreads();
    if (threadIdx.x == 0) {
        float m = red[0];
#pragma unroll
        for (int i = 1; i < 8; i++) m += red[i];
        red[0] = m;
    }
    __syncthreads();
    v = red[0];
    __syncthreads();
    return v;
}

// -------------------- kernel 5: per-row triple softmax, all state in registers --------------------
// one row per CTA, 256 threads, each thread owns 16 elements (8 aligned pairs)
__global__ __launch_bounds__(256) void k_soft(
        const float* __restrict__ adj, const float* __restrict__ adj_ad,
        const float* __restrict__ Wsi, const float* __restrict__ Wei,
        const float* __restrict__ Wri) {
    __shared__ float red[8];
    const int t = threadIdx.x;
    const int row = blockIdx.x;
    const size_t base = (size_t)row * N_NODES;
    const unsigned int encneg = fenc(-1e30f);
    const float wS = fabsf(Wsi[0]), wE = fabsf(Wei[0]), wR = fabsf(Wri[0]);
    const float f1v = g_f1[row];

    const uint2*  lr2  = reinterpret_cast<const uint2*>(g_lr + base);
    const float2* adj2 = reinterpret_cast<const float2*>(adj + base);
    const float2* ad2  = reinterpret_cast<const float2*>(adj_ad + base);
    const float2* f22  = reinterpret_cast<const float2*>(g_f2);

    float ar[16], ae[16];
    float mr = -3.4e38f, me = -3.4e38f;
#pragma unroll
    for (int i = 0; i < 8; i++) {
        int p = t + 256 * i;                // pair index, j = 2p, 2p+1
        uint2 k = lr2[p];
        float2 av = adj2[p];
        float2 f2v = f22[p];
        float lr0 = (k.x == encneg) ? 0.f : fdec(k.x); lr0 = lr0 > 0.f ? lr0 : 0.2f * lr0;
        float lr1 = (k.y == encneg) ? 0.f : fdec(k.y); lr1 = lr1 > 0.f ? lr1 : 0.2f * lr1;
        float a0 = lr0 + av.x, a1 = lr1 + av.y;
        ar[2 * i] = a0; ar[2 * i + 1] = a1;
        mr = fmaxf(mr, fmaxf(a0, a1));
        float g0 = f1v + f2v.x; g0 = g0 > 0.f ? g0 : 0.2f * g0;
        float g1 = f1v + f2v.y; g1 = g1 > 0.f ? g1 : 0.2f * g1;
        float e0 = g0 + av.x, e1 = g1 + av.y;
        ae[2 * i] = e0; ae[2 * i + 1] = e1;
        me = fmaxf(me, fmaxf(e0, e1));
    }
    float Mr = bmax(mr, red), Me = bmax(me, red);

    float sr = 0.f, se = 0.f;
#pragma unroll
    for (int i = 0; i < 16; i++) {
        ar[i] = __expf(ar[i] - Mr); sr += ar[i];
        ae[i] = __expf(ae[i] - Me); se += ae[i];
    }
    float Sr = bsum(sr, red), Se = bsum(se, red);

    const float cE = wE / Se, cR = wR / Sr;
    float mc = -3.4e38f;
#pragma unroll
    for (int i = 0; i < 8; i++) {
        float2 ad = ad2[t + 256 * i];
        float c0 = fmaf(cE, ae[2 * i],     fmaf(cR, ar[2 * i],     wS * ad.x));
        float c1 = fmaf(cE, ae[2 * i + 1], fmaf(cR, ar[2 * i + 1], wS * ad.y));
        ar[2 * i] = c0; ar[2 * i + 1] = c1;
        mc = fmaxf(mc, fmaxf(c0, c1));
    }
    float Mc = bmax(mc, red);

    float su = 0.f;
#pragma unroll
    for (int i = 0; i < 16; i++) { ar[i] = __expf(ar[i] - Mc); su += ar[i]; }
    float Su = bsum(su, red);
    const float inv = 1.f / Su;

    __nv_bfloat162* uh2 = reinterpret_cast<__nv_bfloat162*>(g_Uh + base);
    __nv_bfloat162* ul2 = reinterpret_cast<__nv_bfloat162*>(g_Ul + base);
#pragma unroll
    for (int i = 0; i < 8; i++) {
        float u0 = ar[2 * i] * inv, u1 = ar[2 * i + 1] * inv;
        __nv_bfloat16 h0 = __float2bfloat16(u0), h1 = __float2bfloat16(u1);
        float r0 = u0 - __bfloat162float(h0), r1 = u1 - __bfloat162float(h1);
        uh2[t + 256 * i] = __halves2bfloat162(h0, h1);
        ul2[t + 256 * i] = __halves2bfloat162(__float2bfloat16(r0), __float2bfloat16(r1));
    }
}

// -------------------- kernel 6: out = U @ S via bf16 mma with hi/lo compensation --------------------
__device__ __forceinline__ void mma_bf16(float* c, uint32_t a0, uint32_t a1, uint32_t a2,
                                         uint32_t a3, uint32_t b0, uint32_t b1) {
    asm volatile(
        "mma.sync.aligned.m16n8k16.row.col.f32.bf16.bf16.f32 "
        "{%0,%1,%2,%3},{%4,%5,%6,%7},{%8,%9},{%0,%1,%2,%3};"
        : "+f"(c[0]), "+f"(c[1]), "+f"(c[2]), "+f"(c[3])
        : "r"(a0), "r"(a1), "r"(a2), "r"(a3), "r"(b0), "r"(b1));
}

__global__ __launch_bounds__(256) void k_agg(const float* __restrict__ bias,
                                             float* __restrict__ out) {
    __shared__ float red[8 * 16 * 64];        // 32 KB: per-warp partials
    const int t = threadIdx.x;
    const int w = t >> 5, lane = t & 31;
    const int g = lane >> 2, tig = lane & 3;
    const int m0 = blockIdx.x * 16;

    const __nv_bfloat16* Uh = g_Uh;
    const __nv_bfloat16* Ul = g_Ul;
    const size_t rowA0 = (size_t)(m0 + g) * N_NODES;
    const size_t rowA1 = rowA0 + (size_t)8 * N_NODES;

    float acc[8][4];
#pragma unroll
    for (int nt = 0; nt < 8; nt++)
#pragma unroll
        for (int q = 0; q < 4; q++) acc[nt][q] = 0.f;

    const int kbase = w * 512;
    for (int ks = 0; ks < 32; ks++) {
        const int k0 = kbase + ks * 16 + tig * 2;
        uint32_t ah0 = *reinterpret_cast<const uint32_t*>(Uh + rowA0 + k0);
        uint32_t ah1 = *reinterpret_cast<const uint32_t*>(Uh + rowA1 + k0);
        uint32_t ah2 = *reinterpret_cast<const uint32_t*>(Uh + rowA0 + k0 + 8);
        uint32_t ah3 = *reinterpret_cast<const uint32_t*>(Uh + rowA1 + k0 + 8);
        uint32_t al0 = *reinterpret_cast<const uint32_t*>(Ul + rowA0 + k0);
        uint32_t al1 = *reinterpret_cast<const uint32_t*>(Ul + rowA1 + k0);
        uint32_t al2 = *reinterpret_cast<const uint32_t*>(Ul + rowA0 + k0 + 8);
        uint32_t al3 = *reinterpret_cast<const uint32_t*>(Ul + rowA1 + k0 + 8);
#pragma unroll
        for (int nt = 0; nt < 8; nt++) {
            const size_t bb = (size_t)(nt * 8 + g) * N_NODES + k0;
            uint32_t bh0 = *reinterpret_cast<const uint32_t*>(g_ShT + bb);
            uint32_t bh1 = *reinterpret_cast<const uint32_t*>(g_ShT + bb + 8);
            uint32_t bl0 = *reinterpret_cast<const uint32_t*>(g_SlT + bb);
            uint32_t bl1 = *reinterpret_cast<const uint32_t*>(g_SlT + bb + 8);
            mma_bf16(acc[nt], ah0, ah1, ah2, ah3, bh0, bh1);   // Uh @ Sh
            mma_bf16(acc[nt], ah0, ah1, ah2, ah3, bl0, bl1);   // Uh @ Sl
            mma_bf16(acc[nt], al0, al1, al2, al3, bh0, bh1);   // Ul @ Sh
        }
    }

    // stash per-warp partials, then tree-reduce across the 8 k-chunks
    float* rp = red + w * 1024;
#pragma unroll
    for (int nt = 0; nt < 8; nt++) {
        int c = nt * 8 + tig * 2;
        rp[g * 64 + c]           = acc[nt][0];
        rp[g * 64 + c + 1]       = acc[nt][1];
        rp[(g + 8) * 64 + c]     = acc[nt][2];
        rp[(g + 8) * 64 + c + 1] = acc[nt][3];
    }
    __syncthreads();

    for (int e = t; e < 1024; e += 256) {
        float s = 0.f;
#pragma unroll
        for (int ww = 0; ww < 8; ww++) s += red[ww * 1024 + e];
        int r = e >> 6, c = e & 63;
        float h = s + bias[c];
        out[(size_t)(m0 + r) * F_OUT + c] = (h > 0.f) ? h : expm1f(h);
    }
}

// -------------------- launcher --------------------
extern "C" void kernel_launch(void* const* d_in, const int* in_sizes, int n_in,
                              void* d_out, int out_size) {
    const float* input  = (const float*)d_in[0];
    const float* rel    = (const float*)d_in[1];
    const int*   e1     = (const int*)  d_in[2];
    const int*   e2     = (const int*)  d_in[3];
    const float* adj    = (const float*)d_in[4];
    const float* adj_ad = (const float*)d_in[5];
    const float* Wp     = (const float*)d_in[6];
    const float* wrel   = (const float*)d_in[7];
    const float* wf1    = (const float*)d_in[8];
    const float* bf1    = (const float*)d_in[9];
    const float* wf2    = (const float*)d_in[10];
    const float* bf2    = (const float*)d_in[11];
    const float* bias   = (const float*)d_in[12];
    const float* Wsi    = (const float*)d_in[13];
    const float* Wei    = (const float*)d_in[14];
    const float* Wri    = (const float*)d_in[15];
    float* out = (float*)d_out;

    k_init<<<2048, 256>>>();
    k_gemm<<<N_NODES / 16, 256>>>(input, Wp);
    k_f1f2<<<N_NODES / 4, 128>>>(wf1, bf1, wf2, bf2);
    {
        dim3 g(N_NODES / 256, F_OUT);
        k_split<<<g, 256>>>();
    }
    k_scatter<<<M_EDGES / 256, 256>>>(rel, e1, e2, wrel);
    k_soft<<<N_NODES, 256>>>(adj, adj_ad, Wsi, Wei, Wri);
    k_agg<<<N_NODES / 16, 256>>>(bias, out);
}

// round 4
// speedup vs baseline: 2.1066x; 1.1289x over previous
#include <cuda_runtime.h>
#include <cuda_bf16.h>
#include <cstdint>

#define N_NODES 4096
#define F_IN 512
#define F_OUT 64
#define NREL 16
#define M_EDGES 262144
#define CAP 384          // per-row edge-list capacity (Poisson(128); P(overflow) ~ 0)

// -------------------- scratch (device globals; no allocation) --------------------
__device__ int   g_cnt[N_NODES];                             // per-row edge counts
__device__ uint2 g_elist[(size_t)N_NODES * CAP];             // (col, encoded score)
__device__ float g_seq[(size_t)N_NODES * F_OUT];             // seq_fts fp32
__device__ float g_f1[N_NODES];
__device__ float g_f2[N_NODES];
__device__ __nv_bfloat16 g_Uh[(size_t)N_NODES * N_NODES];    // coefs hi (bf16)
__device__ __nv_bfloat16 g_Ul[(size_t)N_NODES * N_NODES];    // coefs lo (bf16 residual)
__device__ __nv_bfloat16 g_ShT[(size_t)F_OUT * N_NODES];     // seq_fts hi, transposed [f][j]
__device__ __nv_bfloat16 g_SlT[(size_t)F_OUT * N_NODES];     // seq_fts lo, transposed [f][j]

// order-preserving float -> uint encoding; strictly > 0 for all finite floats,
// so 0 is a safe "untouched" sentinel.
__device__ __forceinline__ unsigned int fenc(float f) {
    unsigned int u = __float_as_uint(f);
    return (u & 0x80000000u) ? ~u : (u | 0x80000000u);
}
__device__ __forceinline__ float fdec(unsigned int k) {
    unsigned int u = (k & 0x80000000u) ? (k ^ 0x80000000u) : ~k;
    return __uint_as_float(u);
}

// -------------------- kernel 0: zero the edge cursors --------------------
__global__ void k_zero() { g_cnt[blockIdx.x * 256 + threadIdx.x] = 0; }

// -------------------- kernel 1: rel scores -> per-row edge lists --------------------
__global__ void k_fill(const float* __restrict__ rel, const int* __restrict__ e1,
                       const int* __restrict__ e2, const float* __restrict__ wrel) {
    int m = blockIdx.x * blockDim.x + threadIdx.x;
    if (m >= M_EDGES) return;
    const float4* r4 = reinterpret_cast<const float4*>(rel + (size_t)m * NREL);
    const float4* w4 = reinterpret_cast<const float4*>(wrel);
    float s = 0.f;
#pragma unroll
    for (int i = 0; i < 4; i++) {
        float4 a = r4[i], b = w4[i];
        s += a.x * b.x + a.y * b.y + a.z * b.z + a.w * b.w;
    }
    unsigned int k = fenc(s);
    unsigned int i1 = (unsigned int)e1[m], i2 = (unsigned int)e2[m];
    int a1 = atomicAdd(&g_cnt[i1], 1);
    if (a1 < CAP) g_elist[(size_t)i1 * CAP + a1] = make_uint2(i2, k);
    int a2 = atomicAdd(&g_cnt[i2], 1);
    if (a2 < CAP) g_elist[(size_t)i2 * CAP + a2] = make_uint2(i1, k);
}

// -------------------- kernel 2: seq_fts = input @ W_proj^T --------------------
__global__ void k_gemm(const float* __restrict__ input, const float* __restrict__ W) {
    __shared__ float Ws[32 * 64];   // [kk][f]
    __shared__ float Is[16 * 32];   // [row][kk]
    const int t = threadIdx.x;
    const int row0 = blockIdx.x * 16;
    const int f = t & 63;
    const int rg = t >> 6;
    float acc[4] = {0.f, 0.f, 0.f, 0.f};

    for (int k0 = 0; k0 < F_IN; k0 += 32) {
        __syncthreads();
#pragma unroll
        for (int i = 0; i < 8; i++) {
            int e = t + i * 256;
            int ff = e >> 5, kk = e & 31;
            Ws[kk * 64 + ff] = W[ff * F_IN + k0 + kk];
        }
#pragma unroll
        for (int i = 0; i < 2; i++) {
            int e = t + i * 256;
            int rr = e >> 5, kk = e & 31;
            Is[rr * 32 + kk] = input[(size_t)(row0 + rr) * F_IN + k0 + kk];
        }
        __syncthreads();
#pragma unroll
        for (int kk = 0; kk < 32; kk++) {
            float w = Ws[kk * 64 + f];
#pragma unroll
            for (int i = 0; i < 4; i++)
                acc[i] = fmaf(Is[(rg + 4 * i) * 32 + kk], w, acc[i]);
        }
    }
#pragma unroll
    for (int i = 0; i < 4; i++)
        g_seq[(size_t)(row0 + rg + 4 * i) * F_OUT + f] = acc[i];
}

// -------------------- kernel 3: f1/f2 row dots --------------------
__global__ void k_f1f2(const float* __restrict__ wf1, const float* __restrict__ bf1,
                       const float* __restrict__ wf2, const float* __restrict__ bf2) {
    const int wid = threadIdx.x >> 5, lane = threadIdx.x & 31;
    const int row = blockIdx.x * 4 + wid;
    float a = g_seq[(size_t)row * 64 + lane];
    float b = g_seq[(size_t)row * 64 + 32 + lane];
    float s1 = a * wf1[lane] + b * wf1[32 + lane];
    float s2 = a * wf2[lane] + b * wf2[32 + lane];
#pragma unroll
    for (int o = 16; o; o >>= 1) {
        s1 += __shfl_xor_sync(0xffffffffu, s1, o);
        s2 += __shfl_xor_sync(0xffffffffu, s2, o);
    }
    if (lane == 0) {
        g_f1[row] = s1 + bf1[0];
        g_f2[row] = s2 + bf2[0];
    }
}

// -------------------- kernel 3b: split + transpose seq_fts (coalesced) --------------------
// grid (128, 2), block (32, 8): tile 32 j x 32 f through smem
__global__ void k_split() {
    __shared__ float sm[32][33];
    const int j0 = blockIdx.x * 32, f0 = blockIdx.y * 32;
    const int tx = threadIdx.x, ty = threadIdx.y;
#pragma unroll
    for (int i = 0; i < 4; i++)
        sm[ty + 8 * i][tx] = g_seq[(size_t)(j0 + ty + 8 * i) * F_OUT + f0 + tx];
    __syncthreads();
#pragma unroll
    for (int i = 0; i < 4; i++) {
        int f = f0 + ty + 8 * i, j = j0 + tx;
        float v = sm[tx][ty + 8 * i];
        __nv_bfloat16 h = __float2bfloat16(v);
        g_ShT[(size_t)f * N_NODES + j] = h;
        g_SlT[(size_t)f * N_NODES + j] = __float2bfloat16(v - __bfloat162float(h));
    }
}

// -------------------- block reductions (256 threads, 8 warps) --------------------
__device__ __forceinline__ float bmax(float v, float* red) {
    int lane = threadIdx.x & 31, w = threadIdx.x >> 5;
#pragma unroll
    for (int o = 16; o; o >>= 1) v = fmaxf(v, __shfl_xor_sync(0xffffffffu, v, o));
    if (lane == 0) red[w] = v;
    __syncthreads();
    if (threadIdx.x == 0) {
        float m = red[0];
#pragma unroll
        for (int i = 1; i < 8; i++) m = fmaxf(m, red[i]);
        red[0] = m;
    }
    __syncthreads();
    v = red[0];
    __syncthreads();
    return v;
}
__device__ __forceinline__ float bsum(float v, float* red) {
    int lane = threadIdx.x & 31, w = threadIdx.x >> 5;
#pragma unroll
    for (int o = 16; o; o >>= 1) v += __shfl_xor_sync(0xffffffffu, v, o);
    if (lane == 0) red[w] = v;
    __syncthreads();
    if (threadIdx.x == 0) {
        float m = red[0];
#pragma unroll
        for (int i = 1; i < 8; i++) m += red[i];
        red[0] = m;
    }
    __syncthreads();
    v = red[0];
    __syncthreads();
    return v;
}

// -------------------- kernel 5: per-row triple softmax --------------------
// one row per CTA, 256 threads; relation scores scatter-maxed into smem row buffer
__global__ __launch_bounds__(256) void k_soft(
        const float* __restrict__ adj, const float* __restrict__ adj_ad,
        const float* __restrict__ Wsi, const float* __restrict__ Wei,
        const float* __restrict__ Wri) {
    __shared__ unsigned int rowbuf[N_NODES];   // 16 KB; 0 == untouched
    __shared__ float red[8];
    const int t = threadIdx.x;
    const int row = blockIdx.x;
    const size_t base = (size_t)row * N_NODES;
    const float wS = fabsf(Wsi[0]), wE = fabsf(Wei[0]), wR = fabsf(Wri[0]);
    const float f1v = g_f1[row];

#pragma unroll
    for (int i = 0; i < 16; i++) rowbuf[t + 256 * i] = 0u;
    __syncthreads();
    {
        int cnt = g_cnt[row]; if (cnt > CAP) cnt = CAP;
        const uint2* lst = g_elist + (size_t)row * CAP;
        for (int i = t; i < cnt; i += 256) {
            uint2 e = lst[i];
            atomicMax(&rowbuf[e.x], e.y);
        }
    }
    __syncthreads();

    const float2* adj2 = reinterpret_cast<const float2*>(adj + base);
    const float2* ad2  = reinterpret_cast<const float2*>(adj_ad + base);
    const float2* f22  = reinterpret_cast<const float2*>(g_f2);
    const uint2*  rb2  = reinterpret_cast<const uint2*>(rowbuf);

    float ar[16], ae[16];
    float mr = -3.4e38f, me = -3.4e38f;
#pragma unroll
    for (int i = 0; i < 8; i++) {
        int p = t + 256 * i;                // pair index, j = 2p, 2p+1
        uint2 k = rb2[p];
        float2 av = adj2[p];
        float2 f2v = f22[p];
        float lr0 = (k.x == 0u) ? 0.f : fdec(k.x); lr0 = lr0 > 0.f ? lr0 : 0.2f * lr0;
        float lr1 = (k.y == 0u) ? 0.f : fdec(k.y); lr1 = lr1 > 0.f ? lr1 : 0.2f * lr1;
        float a0 = lr0 + av.x, a1 = lr1 + av.y;
        ar[2 * i] = a0; ar[2 * i + 1] = a1;
        mr = fmaxf(mr, fmaxf(a0, a1));
        float g0 = f1v + f2v.x; g0 = g0 > 0.f ? g0 : 0.2f * g0;
        float g1 = f1v + f2v.y; g1 = g1 > 0.f ? g1 : 0.2f * g1;
        float e0 = g0 + av.x, e1 = g1 + av.y;
        ae[2 * i] = e0; ae[2 * i + 1] = e1;
        me = fmaxf(me, fmaxf(e0, e1));
    }
    float Mr = bmax(mr, red), Me = bmax(me, red);

    float sr = 0.f, se = 0.f;
#pragma unroll
    for (int i = 0; i < 16; i++) {
        ar[i] = __expf(ar[i] - Mr); sr += ar[i];
        ae[i] = __expf(ae[i] - Me); se += ae[i];
    }
    float Sr = bsum(sr, red), Se = bsum(se, red);

    const float cE = wE / Se, cR = wR / Sr;
    float mc = -3.4e38f;
#pragma unroll
    for (int i = 0; i < 8; i++) {
        float2 ad = ad2[t + 256 * i];
        float c0 = fmaf(cE, ae[2 * i],     fmaf(cR, ar[2 * i],     wS * ad.x));
        float c1 = fmaf(cE, ae[2 * i + 1], fmaf(cR, ar[2 * i + 1], wS * ad.y));
        ar[2 * i] = c0; ar[2 * i + 1] = c1;
        mc = fmaxf(mc, fmaxf(c0, c1));
    }
    float Mc = bmax(mc, red);

    float su = 0.f;
#pragma unroll
    for (int i = 0; i < 16; i++) { ar[i] = __expf(ar[i] - Mc); su += ar[i]; }
    float Su = bsum(su, red);
    const float inv = 1.f / Su;

    __nv_bfloat162* uh2 = reinterpret_cast<__nv_bfloat162*>(g_Uh + base);
    __nv_bfloat162* ul2 = reinterpret_cast<__nv_bfloat162*>(g_Ul + base);
#pragma unroll
    for (int i = 0; i < 8; i++) {
        float u0 = ar[2 * i] * inv, u1 = ar[2 * i + 1] * inv;
        __nv_bfloat16 h0 = __float2bfloat16(u0), h1 = __float2bfloat16(u1);
        float r0 = u0 - __bfloat162float(h0), r1 = u1 - __bfloat162float(h1);
        uh2[t + 256 * i] = __halves2bfloat162(h0, h1);
        ul2[t + 256 * i] = __halves2bfloat162(__float2bfloat16(r0), __float2bfloat16(r1));
    }
}

// -------------------- kernel 6: out = U @ S via bf16 mma, 32 rows/CTA --------------------
__device__ __forceinline__ void mma_bf16(float* c, uint32_t a0, uint32_t a1, uint32_t a2,
                                         uint32_t a3, uint32_t b0, uint32_t b1) {
    asm volatile(
        "mma.sync.aligned.m16n8k16.row.col.f32.bf16.bf16.f32 "
        "{%0,%1,%2,%3},{%4,%5,%6,%7},{%8,%9},{%0,%1,%2,%3};"
        : "+f"(c[0]), "+f"(c[1]), "+f"(c[2]), "+f"(c[3])
        : "r"(a0), "r"(a1), "r"(a2), "r"(a3), "r"(b0), "r"(b1));
}

__global__ __launch_bounds__(256) void k_agg(const float* __restrict__ bias,
                                             float* __restrict__ out) {
    extern __shared__ float red[];            // 8 warps * 32 rows * 64 cols = 64 KB
    const int t = threadIdx.x;
    const int w = t >> 5, lane = t & 31;
    const int g = lane >> 2, tig = lane & 3;
    const int m0 = blockIdx.x * 32;

    const size_t rA[4] = { (size_t)(m0 + g)      * N_NODES,
                           (size_t)(m0 + 8 + g)  * N_NODES,
                           (size_t)(m0 + 16 + g) * N_NODES,
                           (size_t)(m0 + 24 + g) * N_NODES };

    float acc[2][8][4];
#pragma unroll
    for (int mt = 0; mt < 2; mt++)
#pragma unroll
        for (int nt = 0; nt < 8; nt++)
#pragma unroll
            for (int q = 0; q < 4; q++) acc[mt][nt][q] = 0.f;

    const int kbase = w * 512;
    for (int ks = 0; ks < 32; ks++) {
        const int k0 = kbase + ks * 16 + tig * 2;
        uint32_t ah[2][4], al[2][4];
#pragma unroll
        for (int mt = 0; mt < 2; mt++) {
            const size_t r0 = rA[2 * mt], r1 = rA[2 * mt + 1];
            ah[mt][0] = *reinterpret_cast<const uint32_t*>(g_Uh + r0 + k0);
            ah[mt][1] = *reinterpret_cast<const uint32_t*>(g_Uh + r1 + k0);
            ah[mt][2] = *reinterpret_cast<const uint32_t*>(g_Uh + r0 + k0 + 8);
            ah[mt][3] = *reinterpret_cast<const uint32_t*>(g_Uh + r1 + k0 + 8);
            al[mt][0] = *reinterpret_cast<const uint32_t*>(g_Ul + r0 + k0);
            al[mt][1] = *reinterpret_cast<const uint32_t*>(g_Ul + r1 + k0);
            al[mt][2] = *reinterpret_cast<const uint32_t*>(g_Ul + r0 + k0 + 8);
            al[mt][3] = *reinterpret_cast<const uint32_t*>(g_Ul + r1 + k0 + 8);
        }
#pragma unroll
        for (int nt = 0; nt < 8; nt++) {
            const size_t bb = (size_t)(nt * 8 + g) * N_NODES + k0;
            uint32_t bh0 = *reinterpret_cast<const uint32_t*>(g_ShT + bb);
            uint32_t bh1 = *reinterpret_cast<const uint32_t*>(g_ShT + bb + 8);
            uint32_t bl0 = *reinterpret_cast<const uint32_t*>(g_SlT + bb);
            uint32_t bl1 = *reinterpret_cast<const uint32_t*>(g_SlT + bb + 8);
#pragma unroll
            for (int mt = 0; mt < 2; mt++) {
                mma_bf16(acc[mt][nt], ah[mt][0], ah[mt][1], ah[mt][2], ah[mt][3], bh0, bh1);
                mma_bf16(acc[mt][nt], ah[mt][0], ah[mt][1], ah[mt][2], ah[mt][3], bl0, bl1);
                mma_bf16(acc[mt][nt], al[mt][0], al[mt][1], al[mt][2], al[mt][3], bh0, bh1);
            }
        }
    }

    // per-warp partials -> smem -> tree reduce over 8 k-chunks
    float* rp = red + w * 2048;
#pragma unroll
    for (int mt = 0; mt < 2; mt++)
#pragma unroll
        for (int nt = 0; nt < 8; nt++) {
            int c = nt * 8 + tig * 2;
            int r0 = mt * 16 + g;
            rp[r0 * 64 + c]           = acc[mt][nt][0];
            rp[r0 * 64 + c + 1]       = acc[mt][nt][1];
            rp[(r0 + 8) * 64 + c]     = acc[mt][nt][2];
            rp[(r0 + 8) * 64 + c + 1] = acc[mt][nt][3];
        }
    __syncthreads();

    for (int e = t; e < 2048; e += 256) {
        float s = 0.f;
#pragma unroll
        for (int ww = 0; ww < 8; ww++) s += red[ww * 2048 + e];
        int r = e >> 6, c = e & 63;
        float h = s + bias[c];
        out[(size_t)(m0 + r) * F_OUT + c] = (h > 0.f) ? h : expm1f(h);
    }
}

// -------------------- launcher --------------------
extern "C" void kernel_launch(void* const* d_in, const int* in_sizes, int n_in,
                              void* d_out, int out_size) {
    const float* input  = (const float*)d_in[0];
    const float* rel    = (const float*)d_in[1];
    const int*   e1     = (const int*)  d_in[2];
    const int*   e2     = (const int*)  d_in[3];
    const float* adj    = (const float*)d_in[4];
    const float* adj_ad = (const float*)d_in[5];
    const float* Wp     = (const float*)d_in[6];
    const float* wrel   = (const float*)d_in[7];
    const float* wf1    = (const float*)d_in[8];
    const float* bf1    = (const float*)d_in[9];
    const float* wf2    = (const float*)d_in[10];
    const float* bf2    = (const float*)d_in[11];
    const float* bias   = (const float*)d_in[12];
    const float* Wsi    = (const float*)d_in[13];
    const float* Wei    = (const float*)d_in[14];
    const float* Wri    = (const float*)d_in[15];
    float* out = (float*)d_out;

    cudaFuncSetAttribute(k_agg, cudaFuncAttributeMaxDynamicSharedMemorySize, 65536);

    k_zero<<<N_NODES / 256, 256>>>();
    k_fill<<<M_EDGES / 256, 256>>>(rel, e1, e2, wrel);
    k_gemm<<<N_NODES / 16, 256>>>(input, Wp);
    k_f1f2<<<N_NODES / 4, 128>>>(wf1, bf1, wf2, bf2);
    {
        dim3 g(N_NODES / 32, F_OUT / 32);
        k_split<<<g, dim3(32, 8)>>>();
    }
    k_soft<<<N_NODES, 256>>>(adj, adj_ad, Wsi, Wei, Wri);
    k_agg<<<N_NODES / 32, 256, 65536>>>(bias, out);
}

// round 6
// speedup vs baseline: 2.1740x; 1.0320x over previous
#include <cuda_runtime.h>
#include <cuda_bf16.h>
#include <cstdint>

#define N_NODES 4096
#define F_IN 512
#define F_OUT 64
#define NREL 16
#define M_EDGES 262144
#define CAP 384          // per-row edge-list capacity (deg ~ Poisson(128))

// -------------------- scratch (device globals; no allocation) --------------------
__device__ int   g_cnt[N_NODES];                             // per-row edge counts
__device__ uint2 g_elist[(size_t)N_NODES * CAP];             // (col, encoded score)
__device__ float g_f1[N_NODES];
__device__ float g_f2[N_NODES];
__device__ __nv_bfloat16 g_Uh[(size_t)N_NODES * N_NODES];    // coefs hi (bf16)
__device__ __nv_bfloat16 g_Ul[(size_t)N_NODES * N_NODES];    // coefs lo (bf16 residual)
__device__ __nv_bfloat16 g_ShT[(size_t)F_OUT * N_NODES];     // seq_fts hi, transposed [f][j]
__device__ __nv_bfloat16 g_SlT[(size_t)F_OUT * N_NODES];     // seq_fts lo, transposed [f][j]

// order-preserving float -> uint encoding; > 0 for all finite floats (0 = untouched)
__device__ __forceinline__ unsigned int fenc(float f) {
    unsigned int u = __float_as_uint(f);
    return (u & 0x80000000u) ? ~u : (u | 0x80000000u);
}
__device__ __forceinline__ float fdec(unsigned int k) {
    unsigned int u = (k & 0x80000000u) ? (k ^ 0x80000000u) : ~k;
    return __uint_as_float(u);
}

// -------------------- kernel 1: prep = GEMM + f1/f2 + bf16 split/transpose + cnt zero ----
// 256 CTAs x 256 thr; CTA handles 16 rows x 64 cols of seq_fts.
__global__ __launch_bounds__(256) void k_prep(
        const float* __restrict__ input, const float* __restrict__ W,
        const float* __restrict__ wf1, const float* __restrict__ bf1,
        const float* __restrict__ wf2, const float* __restrict__ bf2) {
    __shared__ float Ws[32 * 64];   // [kk][f]
    __shared__ float Is[16 * 32];   // [row][kk]
    __shared__ float S[16][65];     // staged seq_fts tile
    const int t = threadIdx.x;
    const int row0 = blockIdx.x * 16;
    const int f = t & 63;
    const int rg = t >> 6;
    float acc[4] = {0.f, 0.f, 0.f, 0.f};

    // zero edge cursors (blocks 0..15 cover 4096)
    int gt = blockIdx.x * 256 + t;
    if (gt < N_NODES) g_cnt[gt] = 0;

    for (int k0 = 0; k0 < F_IN; k0 += 32) {
        __syncthreads();
#pragma unroll
        for (int i = 0; i < 8; i++) {
            int e = t + i * 256;
            int ff = e >> 5, kk = e & 31;
            Ws[kk * 64 + ff] = W[ff * F_IN + k0 + kk];
        }
#pragma unroll
        for (int i = 0; i < 2; i++) {
            int e = t + i * 256;
            int rr = e >> 5, kk = e & 31;
            Is[rr * 32 + kk] = input[(size_t)(row0 + rr) * F_IN + k0 + kk];
        }
        __syncthreads();
#pragma unroll
        for (int kk = 0; kk < 32; kk++) {
            float w = Ws[kk * 64 + f];
#pragma unroll
            for (int i = 0; i < 4; i++)
                acc[i] = fmaf(Is[(rg + 4 * i) * 32 + kk], w, acc[i]);
        }
    }
    __syncthreads();
#pragma unroll
    for (int i = 0; i < 4; i++) S[rg + 4 * i][f] = acc[i];
    __syncthreads();

    // f1/f2: warp w handles rows 2w, 2w+1
    {
        const int w = t >> 5, lane = t & 31;
#pragma unroll
        for (int rr = 0; rr < 2; rr++) {
            int row = 2 * w + rr;
            float a = S[row][lane], b = S[row][lane + 32];
            float s1 = a * wf1[lane] + b * wf1[32 + lane];
            float s2 = a * wf2[lane] + b * wf2[32 + lane];
#pragma unroll
            for (int o = 16; o; o >>= 1) {
                s1 += __shfl_xor_sync(0xffffffffu, s1, o);
                s2 += __shfl_xor_sync(0xffffffffu, s2, o);
            }
            if (lane == 0) {
                g_f1[row0 + row] = s1 + bf1[0];
                g_f2[row0 + row] = s2 + bf2[0];
            }
        }
    }

    // split/transpose: thread t -> f = t>>2, j-quad q = t&3 (rows 4q..4q+3)
    {
        const int ff = t >> 2, q = t & 3;
        unsigned short hs[4], ls[4];
#pragma unroll
        for (int jj = 0; jj < 4; jj++) {
            float v = S[4 * q + jj][ff];
            __nv_bfloat16 h = __float2bfloat16(v);
            hs[jj] = __bfloat16_as_ushort(h);
            ls[jj] = __bfloat16_as_ushort(__float2bfloat16(v - __bfloat162float(h)));
        }
        uint2 hp = make_uint2((uint32_t)hs[0] | ((uint32_t)hs[1] << 16),
                              (uint32_t)hs[2] | ((uint32_t)hs[3] << 16));
        uint2 lp = make_uint2((uint32_t)ls[0] | ((uint32_t)ls[1] << 16),
                              (uint32_t)ls[2] | ((uint32_t)ls[3] << 16));
        *reinterpret_cast<uint2*>(&g_ShT[(size_t)ff * N_NODES + row0 + 4 * q]) = hp;
        *reinterpret_cast<uint2*>(&g_SlT[(size_t)ff * N_NODES + row0 + 4 * q]) = lp;
    }
}

// -------------------- kernel 2: rel scores -> per-row edge lists --------------------
__global__ void k_fill(const float* __restrict__ rel, const int* __restrict__ e1,
                       const int* __restrict__ e2, const float* __restrict__ wrel) {
    int m = blockIdx.x * blockDim.x + threadIdx.x;
    if (m >= M_EDGES) return;
    const float4* r4 = reinterpret_cast<const float4*>(rel + (size_t)m * NREL);
    const float4* w4 = reinterpret_cast<const float4*>(wrel);
    float s = 0.f;
#pragma unroll
    for (int i = 0; i < 4; i++) {
        float4 a = r4[i], b = w4[i];
        s += a.x * b.x + a.y * b.y + a.z * b.z + a.w * b.w;
    }
    unsigned int k = fenc(s);
    unsigned int i1 = (unsigned int)e1[m], i2 = (unsigned int)e2[m];
    int a1 = atomicAdd(&g_cnt[i1], 1);
    if (a1 < CAP) g_elist[(size_t)i1 * CAP + a1] = make_uint2(i2, k);
    int a2 = atomicAdd(&g_cnt[i2], 1);
    if (a2 < CAP) g_elist[(size_t)i2 * CAP + a2] = make_uint2(i1, k);
}

// -------------------- paired block reductions (256 threads, 8 warps) --------------------
__device__ __forceinline__ void bmax2(float& a, float& b, float2* red) {
    int lane = threadIdx.x & 31, w = threadIdx.x >> 5;
#pragma unroll
    for (int o = 16; o; o >>= 1) {
        a = fmaxf(a, __shfl_xor_sync(0xffffffffu, a, o));
        b = fmaxf(b, __shfl_xor_sync(0xffffffffu, b, o));
    }
    if (lane == 0) red[w] = make_float2(a, b);
    __syncthreads();
    if (threadIdx.x == 0) {
        float2 m = red[0];
#pragma unroll
        for (int i = 1; i < 8; i++) { m.x = fmaxf(m.x, red[i].x); m.y = fmaxf(m.y, red[i].y); }
        red[0] = m;
    }
    __syncthreads();
    a = red[0].x; b = red[0].y;
    __syncthreads();
}
__device__ __forceinline__ void bsum2(float& a, float& b, float2* red) {
    int lane = threadIdx.x & 31, w = threadIdx.x >> 5;
#pragma unroll
    for (int o = 16; o; o >>= 1) {
        a += __shfl_xor_sync(0xffffffffu, a, o);
        b += __shfl_xor_sync(0xffffffffu, b, o);
    }
    if (lane == 0) red[w] = make_float2(a, b);
    __syncthreads();
    if (threadIdx.x == 0) {
        float2 m = red[0];
#pragma unroll
        for (int i = 1; i < 8; i++) { m.x += red[i].x; m.y += red[i].y; }
        red[0] = m;
    }
    __syncthreads();
    a = red[0].x; b = red[0].y;
    __syncthreads();
}

// -------------------- kernel 3: per-row triple softmax (vectorized x4) --------------------
__global__ __launch_bounds__(256) void k_soft(
        const float* __restrict__ adj, const float* __restrict__ adj_ad,
        const float* __restrict__ Wsi, const float* __restrict__ Wei,
        const float* __restrict__ Wri) {
    __shared__ unsigned int rowbuf[N_NODES];   // 16 KB; 0 == untouched
    __shared__ float2 red[8];
    const int t = threadIdx.x;
    const int row = blockIdx.x;
    const size_t base = (size_t)row * N_NODES;
    const float wS = fabsf(Wsi[0]), wE = fabsf(Wei[0]), wR = fabsf(Wri[0]);
    const float f1v = g_f1[row];

    // zero + scatter relation scores into the dense row
    {
        uint4 z = make_uint4(0u, 0u, 0u, 0u);
        uint4* rb4 = reinterpret_cast<uint4*>(rowbuf);
#pragma unroll
        for (int i = 0; i < 4; i++) rb4[t + 256 * i] = z;
    }
    __syncthreads();
    {
        int cnt = g_cnt[row]; if (cnt > CAP) cnt = CAP;
        const uint2* lst = g_elist + (size_t)row * CAP;
        for (int i = t; i < cnt; i += 256) {
            uint2 e = lst[i];
            atomicMax(&rowbuf[e.x], e.y);
        }
    }
    __syncthreads();

    const float4* adj4 = reinterpret_cast<const float4*>(adj + base);
    const float4* ad4p = reinterpret_cast<const float4*>(adj_ad + base);
    const float4* f2_4 = reinterpret_cast<const float4*>(g_f2);
    const uint4*  rb4  = reinterpret_cast<const uint4*>(rowbuf);

    float ar[16], ae[16];
    float4 adq[4];                      // adj_ad prefetched during phase 1
    float mr = -3.4e38f, me = -3.4e38f;
#pragma unroll
    for (int i = 0; i < 4; i++) {
        const int p = t + 256 * i;      // quad index: elements 4p..4p+3
        uint4  k4 = rb4[p];
        float4 av = adj4[p];
        float4 fv = f2_4[p];
        adq[i] = ad4p[p];               // early load, consumed in phase 3
        const unsigned int kk[4] = {k4.x, k4.y, k4.z, k4.w};
        const float avv[4] = {av.x, av.y, av.z, av.w};
        const float fvv[4] = {fv.x, fv.y, fv.z, fv.w};
#pragma unroll
        for (int jj = 0; jj < 4; jj++) {
            float lr = (kk[jj] == 0u) ? 0.f : fdec(kk[jj]);
            lr = lr > 0.f ? lr : 0.2f * lr;
            float a = lr + avv[jj];
            ar[4 * i + jj] = a;
            mr = fmaxf(mr, a);
            float g = f1v + fvv[jj]; g = g > 0.f ? g : 0.2f * g;
            float e = g + avv[jj];
            ae[4 * i + jj] = e;
            me = fmaxf(me, e);
        }
    }
    bmax2(mr, me, red);                 // Mr, Me

    float sr = 0.f, se = 0.f;
#pragma unroll
    for (int i = 0; i < 16; i++) {
        ar[i] = __expf(ar[i] - mr); sr += ar[i];
        ae[i] = __expf(ae[i] - me); se += ae[i];
    }
    bsum2(sr, se, red);                 // Sr, Se

    const float cE = wE / se, cR = wR / sr;
    float mc = -3.4e38f, dummy = 0.f;
#pragma unroll
    for (int i = 0; i < 4; i++) {
        const float adv[4] = {adq[i].x, adq[i].y, adq[i].z, adq[i].w};
#pragma unroll
        for (int jj = 0; jj < 4; jj++) {
            float c = fmaf(cE, ae[4 * i + jj], fmaf(cR, ar[4 * i + jj], wS * adv[jj]));
            ar[4 * i + jj] = c;
            mc = fmaxf(mc, c);
        }
    }
    bmax2(mc, dummy, red);              // Mc

    float su = 0.f;
#pragma unroll
    for (int i = 0; i < 16; i++) { ar[i] = __expf(ar[i] - mc); su += ar[i]; }
    float d2 = 0.f;
    bsum2(su, d2, red);                 // Su
    const float inv = 1.f / su;

    uint2* uh2 = reinterpret_cast<uint2*>(g_Uh + base);
    uint2* ul2 = reinterpret_cast<uint2*>(g_Ul + base);
#pragma unroll
    for (int i = 0; i < 4; i++) {
        unsigned short hs[4], ls[4];
#pragma unroll
        for (int jj = 0; jj < 4; jj++) {
            float u = ar[4 * i + jj] * inv;
            __nv_bfloat16 h = __float2bfloat16(u);
            hs[jj] = __bfloat16_as_ushort(h);
            ls[jj] = __bfloat16_as_ushort(__float2bfloat16(u - __bfloat162float(h)));
        }
        uh2[t + 256 * i] = make_uint2((uint32_t)hs[0] | ((uint32_t)hs[1] << 16),
                                      (uint32_t)hs[2] | ((uint32_t)hs[3] << 16));
        ul2[t + 256 * i] = make_uint2((uint32_t)ls[0] | ((uint32_t)ls[1] << 16),
                                      (uint32_t)ls[2] | ((uint32_t)ls[3] << 16));
    }
}

// -------------------- kernel 4: out = U @ S via bf16 mma, 32 rows/CTA --------------------
__device__ __forceinline__ void mma_bf16(float* c, uint32_t a0, uint32_t a1, uint32_t a2,
                                         uint32_t a3, uint32_t b0, uint32_t b1) {
    asm volatile(
        "mma.sync.aligned.m16n8k16.row.col.f32.bf16.bf16.f32 "
        "{%0,%1,%2,%3},{%4,%5,%6,%7},{%8,%9},{%0,%1,%2,%3};"
        : "+f"(c[0]), "+f"(c[1]), "+f"(c[2]), "+f"(c[3])
        : "r"(a0), "r"(a1), "r"(a2), "r"(a3), "r"(b0), "r"(b1));
}

__global__ __launch_bounds__(256) void k_agg(const float* __restrict__ bias,
                                             float* __restrict__ out) {
    extern __shared__ float red[];            // 8 warps * 32 rows * 64 cols = 64 KB
    const int t = threadIdx.x;
    const int w = t >> 5, lane = t & 31;
    const int g = lane >> 2, tig = lane & 3;
    const int m0 = blockIdx.x * 32;

    const size_t rA[4] = { (size_t)(m0 + g)      * N_NODES,
                           (size_t)(m0 + 8 + g)  * N_NODES,
                           (size_t)(m0 + 16 + g) * N_NODES,
                           (size_t)(m0 + 24 + g) * N_NODES };

    float acc[2][8][4];
#pragma unroll
    for (int mt = 0; mt < 2; mt++)
#pragma unroll
        for (int nt = 0; nt < 8; nt++)
#pragma unroll
            for (int q = 0; q < 4; q++) acc[mt][nt][q] = 0.f;

    const int kbase = w * 512;
    for (int ks = 0; ks < 32; ks++) {
        const int k0 = kbase + ks * 16 + tig * 2;
        uint32_t ah[2][4], al[2][4];
#pragma unroll
        for (int mt = 0; mt < 2; mt++) {
            const size_t r0 = rA[2 * mt], r1 = rA[2 * mt + 1];
            ah[mt][0] = *reinterpret_cast<const uint32_t*>(g_Uh + r0 + k0);
            ah[mt][1] = *reinterpret_cast<const uint32_t*>(g_Uh + r1 + k0);
            ah[mt][2] = *reinterpret_cast<const uint32_t*>(g_Uh + r0 + k0 + 8);
            ah[mt][3] = *reinterpret_cast<const uint32_t*>(g_Uh + r1 + k0 + 8);
            al[mt][0] = *reinterpret_cast<const uint32_t*>(g_Ul + r0 + k0);
            al[mt][1] = *reinterpret_cast<const uint32_t*>(g_Ul + r1 + k0);
            al[mt][2] = *reinterpret_cast<const uint32_t*>(g_Ul + r0 + k0 + 8);
            al[mt][3] = *reinterpret_cast<const uint32_t*>(g_Ul + r1 + k0 + 8);
        }
#pragma unroll
        for (int nt = 0; nt < 8; nt++) {
            const size_t bb = (size_t)(nt * 8 + g) * N_NODES + k0;
            uint32_t bh0 = *reinterpret_cast<const uint32_t*>(g_ShT + bb);
            uint32_t bh1 = *reinterpret_cast<const uint32_t*>(g_ShT + bb + 8);
            uint32_t bl0 = *reinterpret_cast<const uint32_t*>(g_SlT + bb);
            uint32_t bl1 = *reinterpret_cast<const uint32_t*>(g_SlT + bb + 8);
#pragma unroll
            for (int mt = 0; mt < 2; mt++) {
                mma_bf16(acc[mt][nt], ah[mt][0], ah[mt][1], ah[mt][2], ah[mt][3], bh0, bh1);
                mma_bf16(acc[mt][nt], ah[mt][0], ah[mt][1], ah[mt][2], ah[mt][3], bl0, bl1);
                mma_bf16(acc[mt][nt], al[mt][0], al[mt][1], al[mt][2], al[mt][3], bh0, bh1);
            }
        }
    }

    float* rp = red + w * 2048;
#pragma unroll
    for (int mt = 0; mt < 2; mt++)
#pragma unroll
        for (int nt = 0; nt < 8; nt++) {
            int c = nt * 8 + tig * 2;
            int r0 = mt * 16 + g;
            rp[r0 * 64 + c]           = acc[mt][nt][0];
            rp[r0 * 64 + c + 1]       = acc[mt][nt][1];
            rp[(r0 + 8) * 64 + c]     = acc[mt][nt][2];
            rp[(r0 + 8) * 64 + c + 1] = acc[mt][nt][3];
        }
    __syncthreads();

    for (int e = t; e < 2048; e += 256) {
        float s = 0.f;
#pragma unroll
        for (int ww = 0; ww < 8; ww++) s += red[ww * 2048 + e];
        int r = e >> 6, c = e & 63;
        float h = s + bias[c];
        out[(size_t)(m0 + r) * F_OUT + c] = (h > 0.f) ? h : expm1f(h);
    }
}

// -------------------- launcher --------------------
extern "C" void kernel_launch(void* const* d_in, const int* in_sizes, int n_in,
                              void* d_out, int out_size) {
    const float* input  = (const float*)d_in[0];
    const float* rel    = (const float*)d_in[1];
    const int*   e1     = (const int*)  d_in[2];
    const int*   e2     = (const int*)  d_in[3];
    const float* adj    = (const float*)d_in[4];
    const float* adj_ad = (const float*)d_in[5];
    const float* Wp     = (const float*)d_in[6];
    const float* wrel   = (const float*)d_in[7];
    const float* wf1    = (const float*)d_in[8];
    const float* bf1    = (const float*)d_in[9];
    const float* wf2    = (const float*)d_in[10];
    const float* bf2    = (const float*)d_in[11];
    const float* bias   = (const float*)d_in[12];
    const float* Wsi    = (const float*)d_in[13];
    const float* Wei    = (const float*)d_in[14];
    const float* Wri    = (const float*)d_in[15];
    float* out = (float*)d_out;

    cudaFuncSetAttribute(k_agg, cudaFuncAttributeMaxDynamicSharedMemorySize, 65536);

    k_prep<<<N_NODES / 16, 256>>>(input, Wp, wf1, bf1, wf2, bf2);
    k_fill<<<M_EDGES / 256, 256>>>(rel, e1, e2, wrel);
    k_soft<<<N_NODES, 256>>>(adj, adj_ad, Wsi, Wei, Wri);
    k_agg<<<N_NODES / 32, 256, 65536>>>(bias, out);
}

// round 7
// speedup vs baseline: 2.5542x; 1.1749x over previous
#include <cuda_runtime.h>
#include <cuda_bf16.h>
#include <cstdint>

#define N_NODES 4096
#define F_IN 512
#define F_OUT 64
#define NREL 16
#define M_EDGES 262144
#define CAP 384          // per-row edge-list capacity (deg ~ Poisson(128))

// -------------------- scratch (device globals; no allocation) --------------------
__device__ int   g_cnt[N_NODES];                             // per-row edge counts
__device__ uint2 g_elist[(size_t)N_NODES * CAP];             // (col, encoded score)
__device__ float g_f1[N_NODES];
__device__ float g_f2[N_NODES];
__device__ __nv_bfloat16 g_Uh[(size_t)N_NODES * N_NODES];    // coefs hi (bf16)
__device__ __nv_bfloat16 g_Ul[(size_t)N_NODES * N_NODES];    // coefs lo (bf16 residual)
__device__ __nv_bfloat16 g_ShT[(size_t)F_OUT * N_NODES];     // seq_fts hi, transposed [f][j]
__device__ __nv_bfloat16 g_SlT[(size_t)F_OUT * N_NODES];     // seq_fts lo, transposed [f][j]

// order-preserving float -> uint encoding; > 0 for all finite floats (0 = untouched)
__device__ __forceinline__ unsigned int fenc(float f) {
    unsigned int u = __float_as_uint(f);
    return (u & 0x80000000u) ? ~u : (u | 0x80000000u);
}
__device__ __forceinline__ float fdec(unsigned int k) {
    unsigned int u = (k & 0x80000000u) ? (k ^ 0x80000000u) : ~k;
    return __uint_as_float(u);
}

// -------------------- kernel 1: prep = GEMM + f1/f2 + bf16 split/transpose + cnt zero ----
__global__ __launch_bounds__(256) void k_prep(
        const float* __restrict__ input, const float* __restrict__ W,
        const float* __restrict__ wf1, const float* __restrict__ bf1,
        const float* __restrict__ wf2, const float* __restrict__ bf2) {
    __shared__ float Ws[32 * 64];   // [kk][f]
    __shared__ float Is[16 * 32];   // [row][kk]
    __shared__ float S[16][65];     // staged seq_fts tile
    const int t = threadIdx.x;
    const int row0 = blockIdx.x * 16;
    const int f = t & 63;
    const int rg = t >> 6;
    float acc[4] = {0.f, 0.f, 0.f, 0.f};

    int gt = blockIdx.x * 256 + t;
    if (gt < N_NODES) g_cnt[gt] = 0;

    for (int k0 = 0; k0 < F_IN; k0 += 32) {
        __syncthreads();
#pragma unroll
        for (int i = 0; i < 8; i++) {
            int e = t + i * 256;
            int ff = e >> 5, kk = e & 31;
            Ws[kk * 64 + ff] = W[ff * F_IN + k0 + kk];
        }
#pragma unroll
        for (int i = 0; i < 2; i++) {
            int e = t + i * 256;
            int rr = e >> 5, kk = e & 31;
            Is[rr * 32 + kk] = input[(size_t)(row0 + rr) * F_IN + k0 + kk];
        }
        __syncthreads();
#pragma unroll
        for (int kk = 0; kk < 32; kk++) {
            float w = Ws[kk * 64 + f];
#pragma unroll
            for (int i = 0; i < 4; i++)
                acc[i] = fmaf(Is[(rg + 4 * i) * 32 + kk], w, acc[i]);
        }
    }
    __syncthreads();
#pragma unroll
    for (int i = 0; i < 4; i++) S[rg + 4 * i][f] = acc[i];
    __syncthreads();

    {
        const int w = t >> 5, lane = t & 31;
#pragma unroll
        for (int rr = 0; rr < 2; rr++) {
            int row = 2 * w + rr;
            float a = S[row][lane], b = S[row][lane + 32];
            float s1 = a * wf1[lane] + b * wf1[32 + lane];
            float s2 = a * wf2[lane] + b * wf2[32 + lane];
#pragma unroll
            for (int o = 16; o; o >>= 1) {
                s1 += __shfl_xor_sync(0xffffffffu, s1, o);
                s2 += __shfl_xor_sync(0xffffffffu, s2, o);
            }
            if (lane == 0) {
                g_f1[row0 + row] = s1 + bf1[0];
                g_f2[row0 + row] = s2 + bf2[0];
            }
        }
    }

    {
        const int ff = t >> 2, q = t & 3;
        unsigned short hs[4], ls[4];
#pragma unroll
        for (int jj = 0; jj < 4; jj++) {
            float v = S[4 * q + jj][ff];
            __nv_bfloat16 h = __float2bfloat16(v);
            hs[jj] = __bfloat16_as_ushort(h);
            ls[jj] = __bfloat16_as_ushort(__float2bfloat16(v - __bfloat162float(h)));
        }
        uint2 hp = make_uint2((uint32_t)hs[0] | ((uint32_t)hs[1] << 16),
                              (uint32_t)hs[2] | ((uint32_t)hs[3] << 16));
        uint2 lp = make_uint2((uint32_t)ls[0] | ((uint32_t)ls[1] << 16),
                              (uint32_t)ls[2] | ((uint32_t)ls[3] << 16));
        *reinterpret_cast<uint2*>(&g_ShT[(size_t)ff * N_NODES + row0 + 4 * q]) = hp;
        *reinterpret_cast<uint2*>(&g_SlT[(size_t)ff * N_NODES + row0 + 4 * q]) = lp;
    }
}

// -------------------- kernel 2: rel scores -> per-row edge lists --------------------
__global__ void k_fill(const float* __restrict__ rel, const int* __restrict__ e1,
                       const int* __restrict__ e2, const float* __restrict__ wrel) {
    int m = blockIdx.x * blockDim.x + threadIdx.x;
    if (m >= M_EDGES) return;
    const float4* r4 = reinterpret_cast<const float4*>(rel + (size_t)m * NREL);
    const float4* w4 = reinterpret_cast<const float4*>(wrel);
    float s = 0.f;
#pragma unroll
    for (int i = 0; i < 4; i++) {
        float4 a = r4[i], b = w4[i];
        s += a.x * b.x + a.y * b.y + a.z * b.z + a.w * b.w;
    }
    unsigned int k = fenc(s);
    unsigned int i1 = (unsigned int)e1[m], i2 = (unsigned int)e2[m];
    int a1 = atomicAdd(&g_cnt[i1], 1);          // both atomics issued before stores: 2x MLP
    int a2 = atomicAdd(&g_cnt[i2], 1);
    if (a1 < CAP) g_elist[(size_t)i1 * CAP + a1] = make_uint2(i2, k);
    if (a2 < CAP) g_elist[(size_t)i2 * CAP + a2] = make_uint2(i1, k);
}

// -------------------- paired block reductions (256 threads, 8 warps) --------------------
__device__ __forceinline__ void bmax2(float& a, float& b, float2* red) {
    int lane = threadIdx.x & 31, w = threadIdx.x >> 5;
#pragma unroll
    for (int o = 16; o; o >>= 1) {
        a = fmaxf(a, __shfl_xor_sync(0xffffffffu, a, o));
        b = fmaxf(b, __shfl_xor_sync(0xffffffffu, b, o));
    }
    if (lane == 0) red[w] = make_float2(a, b);
    __syncthreads();
    if (threadIdx.x == 0) {
        float2 m = red[0];
#pragma unroll
        for (int i = 1; i < 8; i++) { m.x = fmaxf(m.x, red[i].x); m.y = fmaxf(m.y, red[i].y); }
        red[0] = m;
    }
    __syncthreads();
    a = red[0].x; b = red[0].y;
    __syncthreads();
}
__device__ __forceinline__ void bsum2(float& a, float& b, float2* red) {
    int lane = threadIdx.x & 31, w = threadIdx.x >> 5;
#pragma unroll
    for (int o = 16; o; o >>= 1) {
        a += __shfl_xor_sync(0xffffffffu, a, o);
        b += __shfl_xor_sync(0xffffffffu, b, o);
    }
    if (lane == 0) red[w] = make_float2(a, b);
    __syncthreads();
    if (threadIdx.x == 0) {
        float2 m = red[0];
#pragma unroll
        for (int i = 1; i < 8; i++) { m.x += red[i].x; m.y += red[i].y; }
        red[0] = m;
    }
    __syncthreads();
    a = red[0].x; b = red[0].y;
    __syncthreads();
}

// -------------------- kernel 3: per-row triple softmax (low-register version) --------------------
// rowbuf: first holds scattered relation scores (uint), then reused as the e-softmax lane store.
__global__ __launch_bounds__(256) void k_soft(
        const float* __restrict__ adj, const float* __restrict__ adj_ad,
        const float* __restrict__ Wsi, const float* __restrict__ Wei,
        const float* __restrict__ Wri) {
    __shared__ unsigned int rowbuf[N_NODES];   // 16 KB
    __shared__ float2 red[8];
    const int t = threadIdx.x;
    const int row = blockIdx.x;
    const size_t base = (size_t)row * N_NODES;
    const float wS = fabsf(Wsi[0]), wE = fabsf(Wei[0]), wR = fabsf(Wri[0]);
    const float f1v = g_f1[row];

    {
        uint4 z = make_uint4(0u, 0u, 0u, 0u);
        uint4* rb4w = reinterpret_cast<uint4*>(rowbuf);
#pragma unroll
        for (int i = 0; i < 4; i++) rb4w[t + 256 * i] = z;
    }
    __syncthreads();
    {
        int cnt = g_cnt[row]; if (cnt > CAP) cnt = CAP;
        const uint2* lst = g_elist + (size_t)row * CAP;
        for (int i = t; i < cnt; i += 256) {
            uint2 e = lst[i];
            atomicMax(&rowbuf[e.x], e.y);
        }
    }
    __syncthreads();

    const float4* adj4 = reinterpret_cast<const float4*>(adj + base);
    const float4* ad4p = reinterpret_cast<const float4*>(adj_ad + base);
    const float4* f2_4 = reinterpret_cast<const float4*>(g_f2);
    const uint4*  rb4  = reinterpret_cast<const uint4*>(rowbuf);
    float4*       rf4  = reinterpret_cast<float4*>(rowbuf);   // reuse after scatter read

    float ar[16];
    float mr = -3.4e38f, me = -3.4e38f;
#pragma unroll
    for (int i = 0; i < 4; i++) {
        const int p = t + 256 * i;
        uint4  k4 = rb4[p];
        float4 av = adj4[p];
        float4 fv = f2_4[p];
        const unsigned int kk[4] = {k4.x, k4.y, k4.z, k4.w};
        const float avv[4] = {av.x, av.y, av.z, av.w};
        const float fvv[4] = {fv.x, fv.y, fv.z, fv.w};
        float aev[4];
#pragma unroll
        for (int jj = 0; jj < 4; jj++) {
            float lr = (kk[jj] == 0u) ? 0.f : fdec(kk[jj]);
            lr = lr > 0.f ? lr : 0.2f * lr;
            float a = lr + avv[jj];
            ar[4 * i + jj] = a;
            mr = fmaxf(mr, a);
            float g = f1v + fvv[jj]; g = g > 0.f ? g : 0.2f * g;
            float e = g + avv[jj];
            aev[jj] = e;
            me = fmaxf(me, e);
        }
        rf4[p] = make_float4(aev[0], aev[1], aev[2], aev[3]);   // own quad, no race
    }
    bmax2(mr, me, red);                 // Mr, Me

    float sr = 0.f, se = 0.f;
#pragma unroll
    for (int i = 0; i < 4; i++) {
        const int p = t + 256 * i;
        float4 e4 = rf4[p];
        e4.x = __expf(e4.x - me); e4.y = __expf(e4.y - me);
        e4.z = __expf(e4.z - me); e4.w = __expf(e4.w - me);
        se += (e4.x + e4.y) + (e4.z + e4.w);
        rf4[p] = e4;
#pragma unroll
        for (int jj = 0; jj < 4; jj++) {
            ar[4 * i + jj] = __expf(ar[4 * i + jj] - mr);
            sr += ar[4 * i + jj];
        }
    }
    bsum2(sr, se, red);                 // Sr, Se

    const float cE = wE / se, cR = wR / sr;
    float mc = -3.4e38f, dummy = -3.4e38f;
#pragma unroll
    for (int i = 0; i < 4; i++) {
        const int p = t + 256 * i;
        float4 adv = ad4p[p];
        float4 e4 = rf4[p];
        const float advv[4] = {adv.x, adv.y, adv.z, adv.w};
        const float evv[4] = {e4.x, e4.y, e4.z, e4.w};
#pragma unroll
        for (int jj = 0; jj < 4; jj++) {
            float c = fmaf(cE, evv[jj], fmaf(cR, ar[4 * i + jj], wS * advv[jj]));
            ar[4 * i + jj] = c;
            mc = fmaxf(mc, c);
        }
    }
    bmax2(mc, dummy, red);              // Mc

    float su = 0.f, d2 = 0.f;
#pragma unroll
    for (int i = 0; i < 16; i++) { ar[i] = __expf(ar[i] - mc); su += ar[i]; }
    bsum2(su, d2, red);                 // Su
    const float inv = 1.f / su;

    uint2* uh2 = reinterpret_cast<uint2*>(g_Uh + base);
    uint2* ul2 = reinterpret_cast<uint2*>(g_Ul + base);
#pragma unroll
    for (int i = 0; i < 4; i++) {
        unsigned short hs[4], ls[4];
#pragma unroll
        for (int jj = 0; jj < 4; jj++) {
            float u = ar[4 * i + jj] * inv;
            __nv_bfloat16 h = __float2bfloat16(u);
            hs[jj] = __bfloat16_as_ushort(h);
            ls[jj] = __bfloat16_as_ushort(__float2bfloat16(u - __bfloat162float(h)));
        }
        uh2[t + 256 * i] = make_uint2((uint32_t)hs[0] | ((uint32_t)hs[1] << 16),
                                      (uint32_t)hs[2] | ((uint32_t)hs[3] << 16));
        ul2[t + 256 * i] = make_uint2((uint32_t)ls[0] | ((uint32_t)ls[1] << 16),
                                      (uint32_t)ls[2] | ((uint32_t)ls[3] << 16));
    }
}

// -------------------- kernel 4: out = U @ S, smem-staged cp.async + ldmatrix --------------------
#define KC 128                         // k-chunk (bf16 elems)
#define AG_STRIDE 136                  // padded row stride in elems (272 B: conflict-free ldmatrix)
#define AG_STAGE_BYTES (192 * AG_STRIDE * 2)   // Ah32+Al32+Bh64+Bl64 rows = 52224 B

__device__ __forceinline__ uint32_t s2u(const void* p) {
    return (uint32_t)__cvta_generic_to_shared(p);
}
#define LDSM_X4(r, a) asm volatile( \
    "ldmatrix.sync.aligned.m8n8.x4.shared.b16 {%0,%1,%2,%3}, [%4];" \
    : "=r"((r)[0]), "=r"((r)[1]), "=r"((r)[2]), "=r"((r)[3]) : "r"(a))
#define LDSM_X2(r, a) asm volatile( \
    "ldmatrix.sync.aligned.m8n8.x2.shared.b16 {%0,%1}, [%2];" \
    : "=r"((r)[0]), "=r"((r)[1]) : "r"(a))

__device__ __forceinline__ void mma_bf16(float* c, const uint32_t* a, const uint32_t* b) {
    asm volatile(
        "mma.sync.aligned.m16n8k16.row.col.f32.bf16.bf16.f32 "
        "{%0,%1,%2,%3},{%4,%5,%6,%7},{%8,%9},{%0,%1,%2,%3};"
        : "+f"(c[0]), "+f"(c[1]), "+f"(c[2]), "+f"(c[3])
        : "r"(a[0]), "r"(a[1]), "r"(a[2]), "r"(a[3]), "r"(b[0]), "r"(b[1]));
}

__global__ __launch_bounds__(256) void k_agg(const float* __restrict__ bias,
                                             float* __restrict__ out) {
    extern __shared__ __align__(16) unsigned char smraw[];
    __nv_bfloat16* stage0 = reinterpret_cast<__nv_bfloat16*>(smraw);
    __nv_bfloat16* stage1 = reinterpret_cast<__nv_bfloat16*>(smraw + AG_STAGE_BYTES);
    const int t = threadIdx.x;
    const int w = t >> 5, lane = t & 31;
    const int m0 = blockIdx.x * 32;
    const int k0 = w * 16;             // warp's k-slice within each chunk

    float acc[2][8][4];
#pragma unroll
    for (int mt = 0; mt < 2; mt++)
#pragma unroll
        for (int nt = 0; nt < 8; nt++)
#pragma unroll
            for (int q = 0; q < 4; q++) acc[mt][nt][q] = 0.f;

    // --- async stage issue: 3072 x 16B copies, 12 per thread ---
    auto issue = [&](int c) {
        __nv_bfloat16* sb = (c & 1) ? stage1 : stage0;
        const int kc = c * KC;
#pragma unroll
        for (int i = 0; i < 12; i++) {
            int idx = t + 256 * i;
            int r = idx >> 4, seg = idx & 15;
            const __nv_bfloat16* src;
            if (r < 32)       src = g_Uh  + (size_t)(m0 + r) * N_NODES + kc + seg * 8;
            else if (r < 64)  src = g_Ul  + (size_t)(m0 + r - 32) * N_NODES + kc + seg * 8;
            else if (r < 128) src = g_ShT + (size_t)(r - 64) * N_NODES + kc + seg * 8;
            else              src = g_SlT + (size_t)(r - 128) * N_NODES + kc + seg * 8;
            uint32_t dst = s2u(sb + r * AG_STRIDE + seg * 8);
            asm volatile("cp.async.cg.shared.global [%0], [%1], 16;" :: "r"(dst), "l"(src));
        }
        asm volatile("cp.async.commit_group;");
    };

    // ldmatrix per-lane addressing offsets
    const int quad = lane >> 3, rl = lane & 7;
    const int arow = (quad & 1) * 8 + rl;          // A x4: m0/m8 x k0/k8 quads
    const int acol = (quad >> 1) * 8;
    const int bhalf = (lane >> 3) & 1;             // B x2: lanes 0-15 live

    issue(0);
    for (int c = 0; c < 32; c++) {
        if (c + 1 < 32) {
            issue(c + 1);
            asm volatile("cp.async.wait_group 1;");
        } else {
            asm volatile("cp.async.wait_group 0;");
        }
        __syncthreads();
        __nv_bfloat16* sb = (c & 1) ? stage1 : stage0;

        uint32_t ah[2][4], al[2][4];
#pragma unroll
        for (int mt = 0; mt < 2; mt++) {
            LDSM_X4(ah[mt], s2u(sb + (mt * 16 + arow) * AG_STRIDE + k0 + acol));
            LDSM_X4(al[mt], s2u(sb + (32 + mt * 16 + arow) * AG_STRIDE + k0 + acol));
        }
#pragma unroll
        for (int nt = 0; nt < 8; nt++) {
            uint32_t bh[2], bl[2];
            LDSM_X2(bh, s2u(sb + (64 + nt * 8 + rl) * AG_STRIDE + k0 + bhalf * 8));
            LDSM_X2(bl, s2u(sb + (128 + nt * 8 + rl) * AG_STRIDE + k0 + bhalf * 8));
#pragma unroll
            for (int mt = 0; mt < 2; mt++) {
                mma_bf16(acc[mt][nt], ah[mt], bh);   // Uh @ Sh
                mma_bf16(acc[mt][nt], ah[mt], bl);   // Uh @ Sl
                mma_bf16(acc[mt][nt], al[mt], bh);   // Ul @ Sh
            }
        }
        __syncthreads();   // buffer c&1 free for issue(c+2)
    }

    // --- reduce 8 per-warp k-partials via smem (reuse staging) ---
    __syncthreads();
    float* red = reinterpret_cast<float*>(smraw);
    float* rp = red + w * 2048;
    const int gq = lane >> 2, tq = lane & 3;
#pragma unroll
    for (int mt = 0; mt < 2; mt++)
#pragma unroll
        for (int nt = 0; nt < 8; nt++) {
            int cc = nt * 8 + tq * 2;
            int r0 = mt * 16 + gq;
            rp[r0 * 64 + cc]           = acc[mt][nt][0];
            rp[r0 * 64 + cc + 1]       = acc[mt][nt][1];
            rp[(r0 + 8) * 64 + cc]     = acc[mt][nt][2];
            rp[(r0 + 8) * 64 + cc + 1] = acc[mt][nt][3];
        }
    __syncthreads();

    for (int e = t; e < 2048; e += 256) {
        float s = 0.f;
#pragma unroll
        for (int ww = 0; ww < 8; ww++) s += red[ww * 2048 + e];
        int r = e >> 6, cc = e & 63;
        float h = s + bias[cc];
        out[(size_t)(m0 + r) * F_OUT + cc] = (h > 0.f) ? h : expm1f(h);
    }
}

// -------------------- launcher --------------------
extern "C" void kernel_launch(void* const* d_in, const int* in_sizes, int n_in,
                              void* d_out, int out_size) {
    const float* input  = (const float*)d_in[0];
    const float* rel    = (const float*)d_in[1];
    const int*   e1     = (const int*)  d_in[2];
    const int*   e2     = (const int*)  d_in[3];
    const float* adj    = (const float*)d_in[4];
    const float* adj_ad = (const float*)d_in[5];
    const float* Wp     = (const float*)d_in[6];
    const float* wrel   = (const float*)d_in[7];
    const float* wf1    = (const float*)d_in[8];
    const float* bf1    = (const float*)d_in[9];
    const float* wf2    = (const float*)d_in[10];
    const float* bf2    = (const float*)d_in[11];
    const float* bias   = (const float*)d_in[12];
    const float* Wsi    = (const float*)d_in[13];
    const float* Wei    = (const float*)d_in[14];
    const float* Wri    = (const float*)d_in[15];
    float* out = (float*)d_out;

    cudaFuncSetAttribute(k_agg, cudaFuncAttributeMaxDynamicSharedMemorySize,
                         2 * AG_STAGE_BYTES);

    k_prep<<<N_NODES / 16, 256>>>(input, Wp, wf1, bf1, wf2, bf2);
    k_fill<<<M_EDGES / 256, 256>>>(rel, e1, e2, wrel);
    k_soft<<<N_NODES, 256>>>(adj, adj_ad, Wsi, Wei, Wri);
    k_agg<<<N_NODES / 32, 256, 2 * AG_STAGE_BYTES>>>(bias, out);
}

// round 10
// speedup vs baseline: 2.6817x; 1.0499x over previous
#include <cuda_runtime.h>
#include <cuda_bf16.h>
#include <cstdint>

#define N_NODES 4096
#define F_IN 512
#define F_OUT 64
#define NREL 16
#define M_EDGES 262144
#define NBANK 8
#define CAPB 64          // per-(row,bank) capacity; count ~ Poisson(16)

// -------------------- scratch (device globals; no allocation) --------------------
__device__ int   g_cnt[N_NODES * NBANK];                     // banked edge cursors
__device__ uint2 g_elist[(size_t)N_NODES * NBANK * CAPB];    // (col, encoded score)
__device__ float g_f1[N_NODES];
__device__ float g_f2[N_NODES];
__device__ __nv_bfloat16 g_Uh[(size_t)N_NODES * N_NODES];    // coefs hi (bf16)
__device__ __nv_bfloat16 g_Ul[(size_t)N_NODES * N_NODES];    // coefs lo (bf16 residual)
__device__ __nv_bfloat16 g_ShT[(size_t)F_OUT * N_NODES];     // seq_fts hi, transposed [f][j]
__device__ __nv_bfloat16 g_SlT[(size_t)F_OUT * N_NODES];     // seq_fts lo, transposed [f][j]

// order-preserving float -> uint encoding; > 0 for all finite floats (0 = untouched)
__device__ __forceinline__ unsigned int fenc(float f) {
    unsigned int u = __float_as_uint(f);
    return (u & 0x80000000u) ? ~u : (u | 0x80000000u);
}
__device__ __forceinline__ float fdec(unsigned int k) {
    unsigned int u = (k & 0x80000000u) ? (k ^ 0x80000000u) : ~k;
    return __uint_as_float(u);
}

// -------------------- kernel 1: prep = GEMM + f1/f2 + bf16 split/transpose + cnt zero ----
__global__ __launch_bounds__(256) void k_prep(
        const float* __restrict__ input, const float* __restrict__ W,
        const float* __restrict__ wf1, const float* __restrict__ bf1,
        const float* __restrict__ wf2, const float* __restrict__ bf2) {
    __shared__ float Ws[32 * 64];   // [kk][f]
    __shared__ float Is[16 * 32];   // [row][kk]
    __shared__ float S[16][65];     // staged seq_fts tile
    const int t = threadIdx.x;
    const int row0 = blockIdx.x * 16;
    const int f = t & 63;
    const int rg = t >> 6;
    float acc[4] = {0.f, 0.f, 0.f, 0.f};

    // zero banked cursors (256 CTAs x 256 thr = 65536 >= 32768)
    int gt = blockIdx.x * 256 + t;
    if (gt < N_NODES * NBANK) g_cnt[gt] = 0;

    for (int k0 = 0; k0 < F_IN; k0 += 32) {
        __syncthreads();
#pragma unroll
        for (int i = 0; i < 8; i++) {
            int e = t + i * 256;
            int ff = e >> 5, kk = e & 31;
            Ws[kk * 64 + ff] = W[ff * F_IN + k0 + kk];
        }
#pragma unroll
        for (int i = 0; i < 2; i++) {
            int e = t + i * 256;
            int rr = e >> 5, kk = e & 31;
            Is[rr * 32 + kk] = input[(size_t)(row0 + rr) * F_IN + k0 + kk];
        }
        __syncthreads();
#pragma unroll
        for (int kk = 0; kk < 32; kk++) {
            float w = Ws[kk * 64 + f];
#pragma unroll
            for (int i = 0; i < 4; i++)
                acc[i] = fmaf(Is[(rg + 4 * i) * 32 + kk], w, acc[i]);
        }
    }
    __syncthreads();
#pragma unroll
    for (int i = 0; i < 4; i++) S[rg + 4 * i][f] = acc[i];
    __syncthreads();

    {
        const int w = t >> 5, lane = t & 31;
#pragma unroll
        for (int rr = 0; rr < 2; rr++) {
            int row = 2 * w + rr;
            float a = S[row][lane], b = S[row][lane + 32];
            float s1 = a * wf1[lane] + b * wf1[32 + lane];
            float s2 = a * wf2[lane] + b * wf2[32 + lane];
#pragma unroll
            for (int o = 16; o; o >>= 1) {
                s1 += __shfl_xor_sync(0xffffffffu, s1, o);
                s2 += __shfl_xor_sync(0xffffffffu, s2, o);
            }
            if (lane == 0) {
                g_f1[row0 + row] = s1 + bf1[0];
                g_f2[row0 + row] = s2 + bf2[0];
            }
        }
    }

    {
        const int ff = t >> 2, q = t & 3;
        unsigned short hs[4], ls[4];
#pragma unroll
        for (int jj = 0; jj < 4; jj++) {
            float v = S[4 * q + jj][ff];
            __nv_bfloat16 h = __float2bfloat16(v);
            hs[jj] = __bfloat16_as_ushort(h);
            ls[jj] = __bfloat16_as_ushort(__float2bfloat16(v - __bfloat162float(h)));
        }
        uint2 hp = make_uint2((uint32_t)hs[0] | ((uint32_t)hs[1] << 16),
                              (uint32_t)hs[2] | ((uint32_t)hs[3] << 16));
        uint2 lp = make_uint2((uint32_t)ls[0] | ((uint32_t)ls[1] << 16),
                              (uint32_t)ls[2] | ((uint32_t)ls[3] << 16));
        *reinterpret_cast<uint2*>(&g_ShT[(size_t)ff * N_NODES + row0 + 4 * q]) = hp;
        *reinterpret_cast<uint2*>(&g_SlT[(size_t)ff * N_NODES + row0 + 4 * q]) = lp;
    }
}

// -------------------- kernel 2: rel scores -> banked per-row edge lists --------------------
__global__ void k_fill(const float* __restrict__ rel, const int* __restrict__ e1,
                       const int* __restrict__ e2, const float* __restrict__ wrel) {
    int m = blockIdx.x * blockDim.x + threadIdx.x;
    if (m >= M_EDGES) return;
    const float4* r4 = reinterpret_cast<const float4*>(rel + (size_t)m * NREL);
    const float4* w4 = reinterpret_cast<const float4*>(wrel);
    float s = 0.f;
#pragma unroll
    for (int i = 0; i < 4; i++) {
        float4 a = r4[i], b = w4[i];
        s += a.x * b.x + a.y * b.y + a.z * b.z + a.w * b.w;
    }
    unsigned int k = fenc(s);
    unsigned int i1 = (unsigned int)e1[m], i2 = (unsigned int)e2[m];
    const int bank = m & (NBANK - 1);
    int a1 = atomicAdd(&g_cnt[i1 * NBANK + bank], 1);
    int a2 = atomicAdd(&g_cnt[i2 * NBANK + bank], 1);
    if (a1 < CAPB) g_elist[((size_t)i1 * NBANK + bank) * CAPB + a1] = make_uint2(i2, k);
    if (a2 < CAPB) g_elist[((size_t)i2 * NBANK + bank) * CAPB + a2] = make_uint2(i1, k);
}

// -------------------- paired block reductions (256 threads, 8 warps) --------------------
__device__ __forceinline__ void bmax2(float& a, float& b, float2* red) {
    int lane = threadIdx.x & 31, w = threadIdx.x >> 5;
#pragma unroll
    for (int o = 16; o; o >>= 1) {
        a = fmaxf(a, __shfl_xor_sync(0xffffffffu, a, o));
        b = fmaxf(b, __shfl_xor_sync(0xffffffffu, b, o));
    }
    if (lane == 0) red[w] = make_float2(a, b);
    __syncthreads();
    if (threadIdx.x == 0) {
        float2 m = red[0];
#pragma unroll
        for (int i = 1; i < 8; i++) { m.x = fmaxf(m.x, red[i].x); m.y = fmaxf(m.y, red[i].y); }
        red[0] = m;
    }
    __syncthreads();
    a = red[0].x; b = red[0].y;
    __syncthreads();
}
__device__ __forceinline__ void bsum2(float& a, float& b, float2* red) {
    int lane = threadIdx.x & 31, w = threadIdx.x >> 5;
#pragma unroll
    for (int o = 16; o; o >>= 1) {
        a += __shfl_xor_sync(0xffffffffu, a, o);
        b += __shfl_xor_sync(0xffffffffu, b, o);
    }
    if (lane == 0) red[w] = make_float2(a, b);
    __syncthreads();
    if (threadIdx.x == 0) {
        float2 m = red[0];
#pragma unroll
        for (int i = 1; i < 8; i++) { m.x += red[i].x; m.y += red[i].y; }
        red[0] = m;
    }
    __syncthreads();
    a = red[0].x; b = red[0].y;
    __syncthreads();
}

// -------------------- kernel 3: per-row triple softmax --------------------
__global__ __launch_bounds__(256) void k_soft(
        const float* __restrict__ adj, const float* __restrict__ adj_ad,
        const float* __restrict__ Wsi, const float* __restrict__ Wei,
        const float* __restrict__ Wri) {
    __shared__ unsigned int rowbuf[N_NODES];   // 16 KB
    __shared__ float2 red[8];
    const int t = threadIdx.x;
    const int row = blockIdx.x;
    const size_t base = (size_t)row * N_NODES;
    const float wS = fabsf(Wsi[0]), wE = fabsf(Wei[0]), wR = fabsf(Wri[0]);
    const float f1v = g_f1[row];

    {
        uint4 z = make_uint4(0u, 0u, 0u, 0u);
        uint4* rb4w = reinterpret_cast<uint4*>(rowbuf);
#pragma unroll
        for (int i = 0; i < 4; i++) rb4w[t + 256 * i] = z;
    }
    __syncthreads();
    {
        // warp w scatters bank w
        const int w = t >> 5, lane = t & 31;
        int cnt = g_cnt[row * NBANK + w]; if (cnt > CAPB) cnt = CAPB;
        const uint2* lst = g_elist + ((size_t)row * NBANK + w) * CAPB;
        for (int i = lane; i < cnt; i += 32) {
            uint2 e = lst[i];
            atomicMax(&rowbuf[e.x], e.y);
        }
    }
    __syncthreads();

    const float4* adj4 = reinterpret_cast<const float4*>(adj + base);
    const float4* ad4p = reinterpret_cast<const float4*>(adj_ad + base);
    const float4* f2_4 = reinterpret_cast<const float4*>(g_f2);
    const uint4*  rb4  = reinterpret_cast<const uint4*>(rowbuf);
    float4*       rf4  = reinterpret_cast<float4*>(rowbuf);   // reuse after scatter read

    float ar[16];
    float mr = -3.4e38f, me = -3.4e38f;
#pragma unroll
    for (int i = 0; i < 4; i++) {
        const int p = t + 256 * i;
        uint4  k4 = rb4[p];
        float4 av = adj4[p];
        float4 fv = f2_4[p];
        const unsigned int kk[4] = {k4.x, k4.y, k4.z, k4.w};
        const float avv[4] = {av.x, av.y, av.z, av.w};
        const float fvv[4] = {fv.x, fv.y, fv.z, fv.w};
        float aev[4];
#pragma unroll
        for (int jj = 0; jj < 4; jj++) {
            float lr = (kk[jj] == 0u) ? 0.f : fdec(kk[jj]);
            lr = lr > 0.f ? lr : 0.2f * lr;
            float a = lr + avv[jj];
            ar[4 * i + jj] = a;
            mr = fmaxf(mr, a);
            float g = f1v + fvv[jj]; g = g > 0.f ? g : 0.2f * g;
            float e = g + avv[jj];
            aev[jj] = e;
            me = fmaxf(me, e);
        }
        rf4[p] = make_float4(aev[0], aev[1], aev[2], aev[3]);
    }
    bmax2(mr, me, red);                 // Mr, Me

    float sr = 0.f, se = 0.f;
#pragma unroll
    for (int i = 0; i < 4; i++) {
        const int p = t + 256 * i;
        float4 e4 = rf4[p];
        e4.x = __expf(e4.x - me); e4.y = __expf(e4.y - me);
        e4.z = __expf(e4.z - me); e4.w = __expf(e4.w - me);
        se += (e4.x + e4.y) + (e4.z + e4.w);
        rf4[p] = e4;
#pragma unroll
        for (int jj = 0; jj < 4; jj++) {
            ar[4 * i + jj] = __expf(ar[4 * i + jj] - mr);
            sr += ar[4 * i + jj];
        }
    }
    bsum2(sr, se, red);                 // Sr, Se

    const float cE = wE / se, cR = wR / sr;
    float mc = -3.4e38f, dummy = -3.4e38f;
#pragma unroll
    for (int i = 0; i < 4; i++) {
        const int p = t + 256 * i;
        float4 adv = ad4p[p];
        float4 e4 = rf4[p];
        const float advv[4] = {adv.x, adv.y, adv.z, adv.w};
        const float evv[4] = {e4.x, e4.y, e4.z, e4.w};
#pragma unroll
        for (int jj = 0; jj < 4; jj++) {
            float c = fmaf(cE, evv[jj], fmaf(cR, ar[4 * i + jj], wS * advv[jj]));
            ar[4 * i + jj] = c;
            mc = fmaxf(mc, c);
        }
    }
    bmax2(mc, dummy, red);              // Mc

    float su = 0.f, d2 = 0.f;
#pragma unroll
    for (int i = 0; i < 16; i++) { ar[i] = __expf(ar[i] - mc); su += ar[i]; }
    bsum2(su, d2, red);                 // Su
    const float inv = 1.f / su;

    uint2* uh2 = reinterpret_cast<uint2*>(g_Uh + base);
    uint2* ul2 = reinterpret_cast<uint2*>(g_Ul + base);
#pragma unroll
    for (int i = 0; i < 4; i++) {
        unsigned short hs[4], ls[4];
#pragma unroll
        for (int jj = 0; jj < 4; jj++) {
            float u = ar[4 * i + jj] * inv;
            __nv_bfloat16 h = __float2bfloat16(u);
            hs[jj] = __bfloat16_as_ushort(h);
            ls[jj] = __bfloat16_as_ushort(__float2bfloat16(u - __bfloat162float(h)));
        }
        uh2[t + 256 * i] = make_uint2((uint32_t)hs[0] | ((uint32_t)hs[1] << 16),
                                      (uint32_t)hs[2] | ((uint32_t)hs[3] << 16));
        ul2[t + 256 * i] = make_uint2((uint32_t)ls[0] | ((uint32_t)ls[1] << 16),
                                      (uint32_t)ls[2] | ((uint32_t)ls[3] << 16));
    }
}

// -------------------- kernel 4: out = U @ S, 3-stage cp.async pipeline --------------------
#define KC 128                         // k-chunk (bf16 elems)
#define AG_STRIDE 136                  // padded row stride in elems (272 B: conflict-free ldmatrix)
#define AG_STAGE_BYTES (192 * AG_STRIDE * 2)   // 52224 B per stage
#define AG_STAGES 3

__device__ __forceinline__ uint32_t s2u(const void* p) {
    return (uint32_t)__cvta_generic_to_shared(p);
}
#define LDSM_X4(r, a) asm volatile( \
    "ldmatrix.sync.aligned.m8n8.x4.shared.b16 {%0,%1,%2,%3}, [%4];" \
    : "=r"((r)[0]), "=r"((r)[1]), "=r"((r)[2]), "=r"((r)[3]) : "r"(a))
#define LDSM_X2(r, a) asm volatile( \
    "ldmatrix.sync.aligned.m8n8.x2.shared.b16 {%0,%1}, [%2];" \
    : "=r"((r)[0]), "=r"((r)[1]) : "r"(a))

__device__ __forceinline__ void mma_bf16(float* c, const uint32_t* a, const uint32_t* b) {
    asm volatile(
        "mma.sync.aligned.m16n8k16.row.col.f32.bf16.bf16.f32 "
        "{%0,%1,%2,%3},{%4,%5,%6,%7},{%8,%9},{%0,%1,%2,%3};"
        : "+f"(c[0]), "+f"(c[1]), "+f"(c[2]), "+f"(c[3])
        : "r"(a[0]), "r"(a[1]), "r"(a[2]), "r"(a[3]), "r"(b[0]), "r"(b[1]));
}

__global__ __launch_bounds__(256) void k_agg(const float* __restrict__ bias,
                                             float* __restrict__ out) {
    extern __shared__ __align__(16) unsigned char smraw[];
    const int t = threadIdx.x;
    const int w = t >> 5, lane = t & 31;
    const int m0 = blockIdx.x * 32;
    const int k0 = w * 16;             // warp's k-slice within each chunk

    float acc[2][8][4];
#pragma unroll
    for (int mt = 0; mt < 2; mt++)
#pragma unroll
        for (int nt = 0; nt < 8; nt++)
#pragma unroll
            for (int q = 0; q < 4; q++) acc[mt][nt][q] = 0.f;

    auto issue = [&](int c) {
        if (c >= 32) { asm volatile("cp.async.commit_group;"); return; }
        __nv_bfloat16* sb = reinterpret_cast<__nv_bfloat16*>(
            smraw + (size_t)(c % AG_STAGES) * AG_STAGE_BYTES);
        const int kc = c * KC;
#pragma unroll
        for (int i = 0; i < 12; i++) {
            int idx = t + 256 * i;
            int r = idx >> 4, seg = idx & 15;
            const __nv_bfloat16* src;
            if (r < 32)       src = g_Uh  + (size_t)(m0 + r) * N_NODES + kc + seg * 8;
            else if (r < 64)  src = g_Ul  + (size_t)(m0 + r - 32) * N_NODES + kc + seg * 8;
            else if (r < 128) src = g_ShT + (size_t)(r - 64) * N_NODES + kc + seg * 8;
            else              src = g_SlT + (size_t)(r - 128) * N_NODES + kc + seg * 8;
            uint32_t dst = s2u(sb + r * AG_STRIDE + seg * 8);
            asm volatile("cp.async.cg.shared.global [%0], [%1], 16;" :: "r"(dst), "l"(src));
        }
        asm volatile("cp.async.commit_group;");
    };

    const int quad = lane >> 3, rl = lane & 7;
    const int arow = (quad & 1) * 8 + rl;
    const int acol = (quad >> 1) * 8;
    const int bhalf = (lane >> 3) & 1;

    issue(0);
    issue(1);
    for (int c = 0; c < 32; c++) {
        asm volatile("cp.async.wait_group 1;");
        __syncthreads();               // chunk c ready everywhere; c-1 consumed by all warps
        issue(c + 2);                  // overwrites buffer (c-1)%3, now safe
        __nv_bfloat16* sb = reinterpret_cast<__nv_bfloat16*>(
            smraw + (size_t)(c % AG_STAGES) * AG_STAGE_BYTES);

        uint32_t ah[2][4], al[2][4];
#pragma unroll
        for (int mt = 0; mt < 2; mt++) {
            LDSM_X4(ah[mt], s2u(sb + (mt * 16 + arow) * AG_STRIDE + k0 + acol));
            LDSM_X4(al[mt], s2u(sb + (32 + mt * 16 + arow) * AG_STRIDE + k0 + acol));
        }
#pragma unroll
        for (int nt = 0; nt < 8; nt++) {
            uint32_t bh[2], bl[2];
            LDSM_X2(bh, s2u(sb + (64 + nt * 8 + rl) * AG_STRIDE + k0 + bhalf * 8));
            LDSM_X2(bl, s2u(sb + (128 + nt * 8 + rl) * AG_STRIDE + k0 + bhalf * 8));
#pragma unroll
            for (int mt = 0; mt < 2; mt++) {
                mma_bf16(acc[mt][nt], ah[mt], bh);   // Uh @ Sh
                mma_bf16(acc[mt][nt], ah[mt], bl);   // Uh @ Sl
                mma_bf16(acc[mt][nt], al[mt], bh);   // Ul @ Sh
            }
        }
    }

    __syncthreads();
    float* red = reinterpret_cast<float*>(smraw);
    float* rp = red + w * 2048;
    const int gq = lane >> 2, tq = lane & 3;
#pragma unroll
    for (int mt = 0; mt < 2; mt++)
#pragma unroll
        for (int nt = 0; nt < 8; nt++) {
            int cc = nt * 8 + tq * 2;
            int r0 = mt * 16 + gq;
            rp[r0 * 64 + cc]           = acc[mt][nt][0];
            rp[r0 * 64 + cc + 1]       = acc[mt][nt][1];
            rp[(r0 + 8) * 64 + cc]     = acc[mt][nt][2];
            rp[(r0 + 8) * 64 + cc + 1] = acc[mt][nt][3];
        }
    __syncthreads();

    for (int e = t; e < 2048; e += 256) {
        float s = 0.f;
#pragma unroll
        for (int ww = 0; ww < 8; ww++) s += red[ww * 2048 + e];
        int r = e >> 6, cc = e & 63;
        float h = s + bias[cc];
        out[(size_t)(m0 + r) * F_OUT + cc] = (h > 0.f) ? h : expm1f(h);
    }
}

// -------------------- launcher --------------------
extern "C" void kernel_launch(void* const* d_in, const int* in_sizes, int n_in,
                              void* d_out, int out_size) {
    const float* input  = (const float*)d_in[0];
    const float* rel    = (const float*)d_in[1];
    const int*   e1     = (const int*)  d_in[2];
    const int*   e2     = (const int*)  d_in[3];
    const float* adj    = (const float*)d_in[4];
    const float* adj_ad = (const float*)d_in[5];
    const float* Wp     = (const float*)d_in[6];
    const float* wrel   = (const float*)d_in[7];
    const float* wf1    = (const float*)d_in[8];
    const float* bf1    = (const float*)d_in[9];
    const float* wf2    = (const float*)d_in[10];
    const float* bf2    = (const float*)d_in[11];
    const float* bias   = (const float*)d_in[12];
    const float* Wsi    = (const float*)d_in[13];
    const float* Wei    = (const float*)d_in[14];
    const float* Wri    = (const float*)d_in[15];
    float* out = (float*)d_out;

    cudaFuncSetAttribute(k_agg, cudaFuncAttributeMaxDynamicSharedMemorySize,
                         AG_STAGES * AG_STAGE_BYTES);

    k_prep<<<N_NODES / 16, 256>>>(input, Wp, wf1, bf1, wf2, bf2);
    k_fill<<<M_EDGES / 256, 256>>>(rel, e1, e2, wrel);
    k_soft<<<N_NODES, 256>>>(adj, adj_ad, Wsi, Wei, Wri);
    k_agg<<<N_NODES / 32, 256, AG_STAGES * AG_STAGE_BYTES>>>(bias, out);
}

// round 11
// speedup vs baseline: 2.7576x; 1.0283x over previous
#include <cuda_runtime.h>
#include <cuda_bf16.h>
#include <cstdint>

#define N_NODES 4096
#define F_IN 512
#define F_OUT 64
#define NREL 16
#define M_EDGES 262144
#define NBANK 8
#define CAPB 64          // per-(row,bank) capacity; count ~ Poisson(16)

// -------------------- scratch (device globals; no allocation) --------------------
__device__ int   g_cnt[N_NODES * NBANK];                     // banked edge cursors
__device__ uint2 g_elist[(size_t)N_NODES * NBANK * CAPB];    // (col, encoded score)
__device__ float g_f1[N_NODES];
__device__ float g_f2[N_NODES];
__device__ __nv_bfloat16 g_Uh[(size_t)N_NODES * N_NODES];    // coefs hi (bf16)
__device__ __nv_bfloat16 g_Ul[(size_t)N_NODES * N_NODES];    // coefs lo (bf16 residual)
__device__ __nv_bfloat16 g_ShT[(size_t)F_OUT * N_NODES];     // seq_fts hi, transposed [f][j]
__device__ __nv_bfloat16 g_SlT[(size_t)F_OUT * N_NODES];     // seq_fts lo, transposed [f][j]
__device__ float g_part[256 * 32 * F_OUT];                   // split-k partials [bx][32][64]

// order-preserving float -> uint encoding; > 0 for all finite floats (0 = untouched)
__device__ __forceinline__ unsigned int fenc(float f) {
    unsigned int u = __float_as_uint(f);
    return (u & 0x80000000u) ? ~u : (u | 0x80000000u);
}
__device__ __forceinline__ float fdec(unsigned int k) {
    unsigned int u = (k & 0x80000000u) ? (k ^ 0x80000000u) : ~k;
    return __uint_as_float(u);
}

// -------------------- kernel 1: prep = GEMM + f1/f2 + bf16 split/transpose + cnt zero ----
__global__ __launch_bounds__(256) void k_prep(
        const float* __restrict__ input, const float* __restrict__ W,
        const float* __restrict__ wf1, const float* __restrict__ bf1,
        const float* __restrict__ wf2, const float* __restrict__ bf2) {
    __shared__ float Ws[32 * 64];   // [kk][f]
    __shared__ float Is[16 * 32];   // [row][kk]
    __shared__ float S[16][65];     // staged seq_fts tile
    const int t = threadIdx.x;
    const int row0 = blockIdx.x * 16;
    const int f = t & 63;
    const int rg = t >> 6;
    float acc[4] = {0.f, 0.f, 0.f, 0.f};

    int gt = blockIdx.x * 256 + t;
    if (gt < N_NODES * NBANK) g_cnt[gt] = 0;

    for (int k0 = 0; k0 < F_IN; k0 += 32) {
        __syncthreads();
#pragma unroll
        for (int i = 0; i < 8; i++) {
            int e = t + i * 256;
            int ff = e >> 5, kk = e & 31;
            Ws[kk * 64 + ff] = W[ff * F_IN + k0 + kk];
        }
#pragma unroll
        for (int i = 0; i < 2; i++) {
            int e = t + i * 256;
            int rr = e >> 5, kk = e & 31;
            Is[rr * 32 + kk] = input[(size_t)(row0 + rr) * F_IN + k0 + kk];
        }
        __syncthreads();
#pragma unroll
        for (int kk = 0; kk < 32; kk++) {
            float w = Ws[kk * 64 + f];
#pragma unroll
            for (int i = 0; i < 4; i++)
                acc[i] = fmaf(Is[(rg + 4 * i) * 32 + kk], w, acc[i]);
        }
    }
    __syncthreads();
#pragma unroll
    for (int i = 0; i < 4; i++) S[rg + 4 * i][f] = acc[i];
    __syncthreads();

    {
        const int w = t >> 5, lane = t & 31;
#pragma unroll
        for (int rr = 0; rr < 2; rr++) {
            int row = 2 * w + rr;
            float a = S[row][lane], b = S[row][lane + 32];
            float s1 = a * wf1[lane] + b * wf1[32 + lane];
            float s2 = a * wf2[lane] + b * wf2[32 + lane];
#pragma unroll
            for (int o = 16; o; o >>= 1) {
                s1 += __shfl_xor_sync(0xffffffffu, s1, o);
                s2 += __shfl_xor_sync(0xffffffffu, s2, o);
            }
            if (lane == 0) {
                g_f1[row0 + row] = s1 + bf1[0];
                g_f2[row0 + row] = s2 + bf2[0];
            }
        }
    }

    {
        const int ff = t >> 2, q = t & 3;
        unsigned short hs[4], ls[4];
#pragma unroll
        for (int jj = 0; jj < 4; jj++) {
            float v = S[4 * q + jj][ff];
            __nv_bfloat16 h = __float2bfloat16(v);
            hs[jj] = __bfloat16_as_ushort(h);
            ls[jj] = __bfloat16_as_ushort(__float2bfloat16(v - __bfloat162float(h)));
        }
        uint2 hp = make_uint2((uint32_t)hs[0] | ((uint32_t)hs[1] << 16),
                              (uint32_t)hs[2] | ((uint32_t)hs[3] << 16));
        uint2 lp = make_uint2((uint32_t)ls[0] | ((uint32_t)ls[1] << 16),
                              (uint32_t)ls[2] | ((uint32_t)ls[3] << 16));
        *reinterpret_cast<uint2*>(&g_ShT[(size_t)ff * N_NODES + row0 + 4 * q]) = hp;
        *reinterpret_cast<uint2*>(&g_SlT[(size_t)ff * N_NODES + row0 + 4 * q]) = lp;
    }
}

// -------------------- kernel 2: rel scores -> banked per-row edge lists --------------------
__global__ void k_fill(const float* __restrict__ rel, const int* __restrict__ e1,
                       const int* __restrict__ e2, const float* __restrict__ wrel) {
    int m = blockIdx.x * blockDim.x + threadIdx.x;
    if (m >= M_EDGES) return;
    const float4* r4 = reinterpret_cast<const float4*>(rel + (size_t)m * NREL);
    const float4* w4 = reinterpret_cast<const float4*>(wrel);
    float s = 0.f;
#pragma unroll
    for (int i = 0; i < 4; i++) {
        float4 a = r4[i], b = w4[i];
        s += a.x * b.x + a.y * b.y + a.z * b.z + a.w * b.w;
    }
    unsigned int k = fenc(s);
    unsigned int i1 = (unsigned int)e1[m], i2 = (unsigned int)e2[m];
    const int bank = m & (NBANK - 1);
    int a1 = atomicAdd(&g_cnt[i1 * NBANK + bank], 1);
    int a2 = atomicAdd(&g_cnt[i2 * NBANK + bank], 1);
    if (a1 < CAPB) g_elist[((size_t)i1 * NBANK + bank) * CAPB + a1] = make_uint2(i2, k);
    if (a2 < CAPB) g_elist[((size_t)i2 * NBANK + bank) * CAPB + a2] = make_uint2(i1, k);
}

// -------------------- paired block reductions (256 threads, 8 warps) --------------------
__device__ __forceinline__ void bmax2(float& a, float& b, float2* red) {
    int lane = threadIdx.x & 31, w = threadIdx.x >> 5;
#pragma unroll
    for (int o = 16; o; o >>= 1) {
        a = fmaxf(a, __shfl_xor_sync(0xffffffffu, a, o));
        b = fmaxf(b, __shfl_xor_sync(0xffffffffu, b, o));
    }
    if (lane == 0) red[w] = make_float2(a, b);
    __syncthreads();
    if (threadIdx.x == 0) {
        float2 m = red[0];
#pragma unroll
        for (int i = 1; i < 8; i++) { m.x = fmaxf(m.x, red[i].x); m.y = fmaxf(m.y, red[i].y); }
        red[0] = m;
    }
    __syncthreads();
    a = red[0].x; b = red[0].y;
    __syncthreads();
}
__device__ __forceinline__ void bsum2(float& a, float& b, float2* red) {
    int lane = threadIdx.x & 31, w = threadIdx.x >> 5;
#pragma unroll
    for (int o = 16; o; o >>= 1) {
        a += __shfl_xor_sync(0xffffffffu, a, o);
        b += __shfl_xor_sync(0xffffffffu, b, o);
    }
    if (lane == 0) red[w] = make_float2(a, b);
    __syncthreads();
    if (threadIdx.x == 0) {
        float2 m = red[0];
#pragma unroll
        for (int i = 1; i < 8; i++) { m.x += red[i].x; m.y += red[i].y; }
        red[0] = m;
    }
    __syncthreads();
    a = red[0].x; b = red[0].y;
    __syncthreads();
}

// -------------------- kernel 3: per-row triple softmax --------------------
__global__ __launch_bounds__(256) void k_soft(
        const float* __restrict__ adj, const float* __restrict__ adj_ad,
        const float* __restrict__ Wsi, const float* __restrict__ Wei,
        const float* __restrict__ Wri) {
    __shared__ unsigned int rowbuf[N_NODES];   // 16 KB
    __shared__ float2 red[8];
    const int t = threadIdx.x;
    const int row = blockIdx.x;
    const size_t base = (size_t)row * N_NODES;
    const float wS = fabsf(Wsi[0]), wE = fabsf(Wei[0]), wR = fabsf(Wri[0]);
    const float f1v = g_f1[row];

    {
        uint4 z = make_uint4(0u, 0u, 0u, 0u);
        uint4* rb4w = reinterpret_cast<uint4*>(rowbuf);
#pragma unroll
        for (int i = 0; i < 4; i++) rb4w[t + 256 * i] = z;
    }
    __syncthreads();
    {
        const int w = t >> 5, lane = t & 31;
        int cnt = g_cnt[row * NBANK + w]; if (cnt > CAPB) cnt = CAPB;
        const uint2* lst = g_elist + ((size_t)row * NBANK + w) * CAPB;
        for (int i = lane; i < cnt; i += 32) {
            uint2 e = lst[i];
            atomicMax(&rowbuf[e.x], e.y);
        }
    }
    __syncthreads();

    const float4* adj4 = reinterpret_cast<const float4*>(adj + base);
    const float4* ad4p = reinterpret_cast<const float4*>(adj_ad + base);
    const float4* f2_4 = reinterpret_cast<const float4*>(g_f2);
    const uint4*  rb4  = reinterpret_cast<const uint4*>(rowbuf);
    float4*       rf4  = reinterpret_cast<float4*>(rowbuf);

    float ar[16];
    float mr = -3.4e38f, me = -3.4e38f;
#pragma unroll
    for (int i = 0; i < 4; i++) {
        const int p = t + 256 * i;
        uint4  k4 = rb4[p];
        float4 av = __ldcs(&adj4[p]);        // streamed, evict-first
        float4 fv = f2_4[p];
        const unsigned int kk[4] = {k4.x, k4.y, k4.z, k4.w};
        const float avv[4] = {av.x, av.y, av.z, av.w};
        const float fvv[4] = {fv.x, fv.y, fv.z, fv.w};
        float aev[4];
#pragma unroll
        for (int jj = 0; jj < 4; jj++) {
            float lr = (kk[jj] == 0u) ? 0.f : fdec(kk[jj]);
            lr = lr > 0.f ? lr : 0.2f * lr;
            float a = lr + avv[jj];
            ar[4 * i + jj] = a;
            mr = fmaxf(mr, a);
            float g = f1v + fvv[jj]; g = g > 0.f ? g : 0.2f * g;
            float e = g + avv[jj];
            aev[jj] = e;
            me = fmaxf(me, e);
        }
        rf4[p] = make_float4(aev[0], aev[1], aev[2], aev[3]);
    }
    bmax2(mr, me, red);                 // Mr, Me

    float sr = 0.f, se = 0.f;
#pragma unroll
    for (int i = 0; i < 4; i++) {
        const int p = t + 256 * i;
        float4 e4 = rf4[p];
        e4.x = __expf(e4.x - me); e4.y = __expf(e4.y - me);
        e4.z = __expf(e4.z - me); e4.w = __expf(e4.w - me);
        se += (e4.x + e4.y) + (e4.z + e4.w);
        rf4[p] = e4;
#pragma unroll
        for (int jj = 0; jj < 4; jj++) {
            ar[4 * i + jj] = __expf(ar[4 * i + jj] - mr);
            sr += ar[4 * i + jj];
        }
    }
    bsum2(sr, se, red);                 // Sr, Se

    const float cE = wE / se, cR = wR / sr;
    float mc = -3.4e38f, dummy = -3.4e38f;
#pragma unroll
    for (int i = 0; i < 4; i++) {
        const int p = t + 256 * i;
        float4 adv = __ldcs(&ad4p[p]);       // streamed, evict-first
        float4 e4 = rf4[p];
        const float advv[4] = {adv.x, adv.y, adv.z, adv.w};
        const float evv[4] = {e4.x, e4.y, e4.z, e4.w};
#pragma unroll
        for (int jj = 0; jj < 4; jj++) {
            float c = fmaf(cE, evv[jj], fmaf(cR, ar[4 * i + jj], wS * advv[jj]));
            ar[4 * i + jj] = c;
            mc = fmaxf(mc, c);
        }
    }
    bmax2(mc, dummy, red);              // Mc

    float su = 0.f, d2 = 0.f;
#pragma unroll
    for (int i = 0; i < 16; i++) { ar[i] = __expf(ar[i] - mc); su += ar[i]; }
    bsum2(su, d2, red);                 // Su
    const float inv = 1.f / su;

    uint2* uh2 = reinterpret_cast<uint2*>(g_Uh + base);
    uint2* ul2 = reinterpret_cast<uint2*>(g_Ul + base);
#pragma unroll
    for (int i = 0; i < 4; i++) {
        unsigned short hs[4], ls[4];
#pragma unroll
        for (int jj = 0; jj < 4; jj++) {
            float u = ar[4 * i + jj] * inv;
            __nv_bfloat16 h = __float2bfloat16(u);
            hs[jj] = __bfloat16_as_ushort(h);
            ls[jj] = __bfloat16_as_ushort(__float2bfloat16(u - __bfloat162float(h)));
        }
        uh2[t + 256 * i] = make_uint2((uint32_t)hs[0] | ((uint32_t)hs[1] << 16),
                                      (uint32_t)hs[2] | ((uint32_t)hs[3] << 16));
        ul2[t + 256 * i] = make_uint2((uint32_t)ls[0] | ((uint32_t)ls[1] << 16),
                                      (uint32_t)ls[2] | ((uint32_t)ls[3] << 16));
    }
}

// -------------------- kernel 4: U @ S partials, split-K x2, 2 CTAs/SM --------------------
#define KC 64                          // k-chunk (bf16 elems)
#define AG_STRIDE 72                   // padded row stride (144 B: conflict-free ldmatrix)
#define AG_STAGE_BYTES (192 * AG_STRIDE * 2)   // 27648 B per stage
#define AG_STAGES 3
#define NCHUNK 32                      // 32 x 64 = 2048 = half of K

__device__ __forceinline__ uint32_t s2u(const void* p) {
    return (uint32_t)__cvta_generic_to_shared(p);
}
#define LDSM_X4(r, a) asm volatile( \
    "ldmatrix.sync.aligned.m8n8.x4.shared.b16 {%0,%1,%2,%3}, [%4];" \
    : "=r"((r)[0]), "=r"((r)[1]), "=r"((r)[2]), "=r"((r)[3]) : "r"(a))
#define LDSM_X2(r, a) asm volatile( \
    "ldmatrix.sync.aligned.m8n8.x2.shared.b16 {%0,%1}, [%2];" \
    : "=r"((r)[0]), "=r"((r)[1]) : "r"(a))

__device__ __forceinline__ void mma_bf16(float* c, const uint32_t* a, const uint32_t* b) {
    asm volatile(
        "mma.sync.aligned.m16n8k16.row.col.f32.bf16.bf16.f32 "
        "{%0,%1,%2,%3},{%4,%5,%6,%7},{%8,%9},{%0,%1,%2,%3};"
        : "+f"(c[0]), "+f"(c[1]), "+f"(c[2]), "+f"(c[3])
        : "r"(a[0]), "r"(a[1]), "r"(a[2]), "r"(a[3]), "r"(b[0]), "r"(b[1]));
}

__global__ __launch_bounds__(256, 2) void k_agg() {
    extern __shared__ __align__(16) unsigned char smraw[];
    const int t = threadIdx.x;
    const int w = t >> 5, lane = t & 31;
    const int mtile = blockIdx.x >> 1;
    const int ks = blockIdx.x & 1;
    const int m0 = mtile * 32;
    const int kw = (w & 3) * 16;       // warp's k-slice within the 64-wide chunk
    const int ntg = w >> 2;            // warp's nt group (0 or 1) -> 4 nt each

    float acc[2][4][4];
#pragma unroll
    for (int mt = 0; mt < 2; mt++)
#pragma unroll
        for (int nt = 0; nt < 4; nt++)
#pragma unroll
            for (int q = 0; q < 4; q++) acc[mt][nt][q] = 0.f;

    auto issue = [&](int c) {
        if (c >= NCHUNK) { asm volatile("cp.async.commit_group;"); return; }
        __nv_bfloat16* sb = reinterpret_cast<__nv_bfloat16*>(
            smraw + (size_t)(c % AG_STAGES) * AG_STAGE_BYTES);
        const int kc = ks * 2048 + c * KC;
#pragma unroll
        for (int i = 0; i < 6; i++) {          // 1536 x 16B copies
            int idx = t + 256 * i;
            int r = idx >> 3, seg = idx & 7;   // 8 x 16B segments per 64-elem row
            const __nv_bfloat16* src;
            if (r < 32)       src = g_Uh  + (size_t)(m0 + r) * N_NODES + kc + seg * 8;
            else if (r < 64)  src = g_Ul  + (size_t)(m0 + r - 32) * N_NODES + kc + seg * 8;
            else if (r < 128) src = g_ShT + (size_t)(r - 64) * N_NODES + kc + seg * 8;
            else              src = g_SlT + (size_t)(r - 128) * N_NODES + kc + seg * 8;
            uint32_t dst = s2u(sb + r * AG_STRIDE + seg * 8);
            asm volatile("cp.async.cg.shared.global [%0], [%1], 16;" :: "r"(dst), "l"(src));
        }
        asm volatile("cp.async.commit_group;");
    };

    const int quad = lane >> 3, rl = lane & 7;
    const int arow = (quad & 1) * 8 + rl;
    const int acol = (quad >> 1) * 8;
    const int bhalf = (lane >> 3) & 1;

    issue(0);
    issue(1);
    for (int c = 0; c < NCHUNK; c++) {
        asm volatile("cp.async.wait_group 1;");
        __syncthreads();
        issue(c + 2);
        __nv_bfloat16* sb = reinterpret_cast<__nv_bfloat16*>(
            smraw + (size_t)(c % AG_STAGES) * AG_STAGE_BYTES);

        uint32_t ah[2][4], al[2][4];
#pragma unroll
        for (int mt = 0; mt < 2; mt++) {
            LDSM_X4(ah[mt], s2u(sb + (mt * 16 + arow) * AG_STRIDE + kw + acol));
            LDSM_X4(al[mt], s2u(sb + (32 + mt * 16 + arow) * AG_STRIDE + kw + acol));
        }
#pragma unroll
        for (int nt = 0; nt < 4; nt++) {
            const int fr = (ntg * 4 + nt) * 8 + rl;
            uint32_t bh[2], bl[2];
            LDSM_X2(bh, s2u(sb + (64 + fr) * AG_STRIDE + kw + bhalf * 8));
            LDSM_X2(bl, s2u(sb + (128 + fr) * AG_STRIDE + kw + bhalf * 8));
#pragma unroll
            for (int mt = 0; mt < 2; mt++) {
                mma_bf16(acc[mt][nt], ah[mt], bh);   // Uh @ Sh
                mma_bf16(acc[mt][nt], ah[mt], bl);   // Uh @ Sl
                mma_bf16(acc[mt][nt], al[mt], bh);   // Ul @ Sh
            }
        }
    }

    // reduce 4 k-slice warps per nt-group via smem (reuse staging; 32 KB)
    __syncthreads();
    float* red = reinterpret_cast<float*>(smraw);
    float* rp = red + w * 1024;                // per-warp 32 rows x 32 cols
    const int gq = lane >> 2, tq = lane & 3;
#pragma unroll
    for (int mt = 0; mt < 2; mt++)
#pragma unroll
        for (int nt = 0; nt < 4; nt++) {
            int cc = nt * 8 + tq * 2;
            int r0 = mt * 16 + gq;
            rp[r0 * 32 + cc]           = acc[mt][nt][0];
            rp[r0 * 32 + cc + 1]       = acc[mt][nt][1];
            rp[(r0 + 8) * 32 + cc]     = acc[mt][nt][2];
            rp[(r0 + 8) * 32 + cc + 1] = acc[mt][nt][3];
        }
    __syncthreads();

    float* part = g_part + (size_t)blockIdx.x * 2048;
    for (int e = t; e < 2048; e += 256) {
        int r = e >> 6, c = e & 63;
        int ng = c >> 5, cl = c & 31;
        float s = 0.f;
#pragma unroll
        for (int ww = 0; ww < 4; ww++) s += red[(ng * 4 + ww) * 1024 + r * 32 + cl];
        part[e] = s;
    }
}

// -------------------- kernel 5: combine split-k partials + bias + elu --------------------
__global__ __launch_bounds__(256) void k_fin(const float* __restrict__ bias,
                                             float* __restrict__ out) {
    const int idx = blockIdx.x * 256 + threadIdx.x;        // 65536 float4s
    const int mtile = idx >> 9;                            // 512 float4s per m-tile
    const int e4 = idx & 511;                              // within-tile float4 index
    const float4* p0 = reinterpret_cast<const float4*>(g_part + (size_t)(mtile * 2) * 2048);
    const float4* p1 = reinterpret_cast<const float4*>(g_part + (size_t)(mtile * 2 + 1) * 2048);
    const float4* b4 = reinterpret_cast<const float4*>(bias);
    float4 a = p0[e4], b = p1[e4], bb = b4[e4 & 15];
    float4 h;
    h.x = a.x + b.x + bb.x; h.y = a.y + b.y + bb.y;
    h.z = a.z + b.z + bb.z; h.w = a.w + b.w + bb.w;
    h.x = h.x > 0.f ? h.x : expm1f(h.x);
    h.y = h.y > 0.f ? h.y : expm1f(h.y);
    h.z = h.z > 0.f ? h.z : expm1f(h.z);
    h.w = h.w > 0.f ? h.w : expm1f(h.w);
    reinterpret_cast<float4*>(out)[idx] = h;
}

// -------------------- launcher --------------------
extern "C" void kernel_launch(void* const* d_in, const int* in_sizes, int n_in,
                              void* d_out, int out_size) {
    const float* input  = (const float*)d_in[0];
    const float* rel    = (const float*)d_in[1];
    const int*   e1     = (const int*)  d_in[2];
    const int*   e2     = (const int*)  d_in[3];
    const float* adj    = (const float*)d_in[4];
    const float* adj_ad = (const float*)d_in[5];
    const float* Wp     = (const float*)d_in[6];
    const float* wrel   = (const float*)d_in[7];
    const float* wf1    = (const float*)d_in[8];
    const float* bf1    = (const float*)d_in[9];
    const float* wf2    = (const float*)d_in[10];
    const float* bf2    = (const float*)d_in[11];
    const float* bias   = (const float*)d_in[12];
    const float* Wsi    = (const float*)d_in[13];
    const float* Wei    = (const float*)d_in[14];
    const float* Wri    = (const float*)d_in[15];
    float* out = (float*)d_out;

    cudaFuncSetAttribute(k_agg, cudaFuncAttributeMaxDynamicSharedMemorySize,
                         AG_STAGES * AG_STAGE_BYTES);

    k_prep<<<N_NODES / 16, 256>>>(input, Wp, wf1, bf1, wf2, bf2);
    k_fill<<<M_EDGES / 256, 256>>>(rel, e1, e2, wrel);
    k_soft<<<N_NODES, 256>>>(adj, adj_ad, Wsi, Wei, Wri);
    k_agg<<<256, 256, AG_STAGES * AG_STAGE_BYTES>>>();
    k_fin<<<256, 256>>>(bias, out);
}